// round 2
// baseline (speedup 1.0000x reference)
#include <cuda_runtime.h>
#include <math.h>

// ---------------------------------------------------------------------------
// GCN encoder stack:
//   z   = relu(A1n(relu(A1n(x W1)+b1) W2)+b2)
//   z_g = relu(A2n(relu((A2n z) W3 + b3) W4)+b4)   (layer3 reordered: A(zW)= (Az)W)
// A*n = D^-1/2 (A+I) D^-1/2 applied edge-wise + self-loop term.
// ---------------------------------------------------------------------------

#define NMAX 50048

__device__ float g_b512a[(size_t)NMAX * 512];
__device__ float g_b512b[(size_t)NMAX * 512];
__device__ float g_b256a[(size_t)NMAX * 256];
__device__ float g_b256b[(size_t)NMAX * 256];
__device__ int   g_deg1[NMAX];
__device__ int   g_deg2[NMAX];
__device__ float g_inv1[NMAX];
__device__ float g_inv2[NMAX];

// ---------------------------------------------------------------------------
// helpers
// ---------------------------------------------------------------------------
__device__ __forceinline__ void red_add_v4(float* addr, float4 v) {
    // sm_90+ vectorized fp32 global reduction (PTX ISA 8.1+)
    asm volatile("red.global.add.v4.f32 [%0], {%1, %2, %3, %4};"
                 :: "l"(addr), "f"(v.x), "f"(v.y), "f"(v.z), "f"(v.w)
                 : "memory");
}

// ---------------------------------------------------------------------------
// degree / normalization
// ---------------------------------------------------------------------------
__global__ void k_zero_deg(int* d1, int* d2, int n) {
    int i = blockIdx.x * blockDim.x + threadIdx.x;
    if (i < n) { d1[i] = 0; d2[i] = 0; }
}

__global__ void k_deg(const int* __restrict__ dst, int E, int* deg) {
    int i = blockIdx.x * blockDim.x + threadIdx.x;
    if (i < E) atomicAdd(&deg[dst[i]], 1);
}

__global__ void k_inv(const int* __restrict__ d1, const int* __restrict__ d2,
                      float* i1, float* i2, int n) {
    int i = blockIdx.x * blockDim.x + threadIdx.x;
    if (i < n) {
        i1[i] = rsqrtf((float)d1[i] + 1.0f);
        i2[i] = rsqrtf((float)d2[i] + 1.0f);
    }
}

// ---------------------------------------------------------------------------
// agg init: agg[i,:] = h[i,:] * inv[i]^2 (+ bias)   (self-loop + bias term)
// ---------------------------------------------------------------------------
template<int D>
__global__ void k_init_agg(const float* __restrict__ h, const float* __restrict__ inv,
                           const float* __restrict__ bias, float* __restrict__ agg, int n) {
    constexpr int C4 = D / 4;
    int idx = blockIdx.x * blockDim.x + threadIdx.x;
    if (idx >= n * C4) return;
    int row = idx / C4;
    int col = idx - row * C4;
    float s = inv[row]; s *= s;
    float4 v = ((const float4*)h)[idx];
    float4 o;
    if (bias) {
        float4 b = ((const float4*)bias)[col];
        o = make_float4(v.x * s + b.x, v.y * s + b.y, v.z * s + b.z, v.w * s + b.w);
    } else {
        o = make_float4(v.x * s, v.y * s, v.z * s, v.w * s);
    }
    ((float4*)agg)[idx] = o;
}

// ---------------------------------------------------------------------------
// edge scatter: agg[dst,:] += h[src,:] * inv[src]*inv[dst]
// ---------------------------------------------------------------------------
template<int D>
__global__ __launch_bounds__(256)
void k_scatter(const int* __restrict__ src, const int* __restrict__ dst,
               const float* __restrict__ inv, const float* __restrict__ h,
               float* agg, int E) {
    constexpr int TPE  = D / 4;       // threads per edge (float4 lanes)
    constexpr int EPB  = 256 / TPE;   // edges in flight per block
    constexpr int ITER = 8;
    int lane = threadIdx.x & (TPE - 1);
    int sub  = threadIdx.x / TPE;
    int base = blockIdx.x * (EPB * ITER) + sub;
#pragma unroll
    for (int it = 0; it < ITER; it++) {
        int e = base + it * EPB;
        if (e < E) {
            int s = src[e], d = dst[e];
            float c = inv[s] * inv[d];
            float4 v = *(const float4*)(h + (size_t)s * D + lane * 4);
            red_add_v4(agg + (size_t)d * D + lane * 4,
                       make_float4(v.x * c, v.y * c, v.z * c, v.w * c));
        }
    }
}

// ---------------------------------------------------------------------------
// relu copy (in==out allowed)
// ---------------------------------------------------------------------------
__global__ void k_relu(const float* __restrict__ in, float* __restrict__ out, int n4) {
    int i = blockIdx.x * blockDim.x + threadIdx.x;
    if (i >= n4) return;
    float4 v = ((const float4*)in)[i];
    v.x = fmaxf(v.x, 0.f); v.y = fmaxf(v.y, 0.f);
    v.z = fmaxf(v.z, 0.f); v.w = fmaxf(v.w, 0.f);
    ((float4*)out)[i] = v;
}

// ---------------------------------------------------------------------------
// SGEMM: C[M,N] = A[M,K] * B[K,N] (+bias, +relu). 128x128x8 tiles, 256 thr,
// 8x8 per thread. N,K multiples of 128/8; M guarded.
// ---------------------------------------------------------------------------
template<bool HAS_BIAS, bool RELU>
__global__ __launch_bounds__(256)
void k_sgemm(const float* __restrict__ A, const float* __restrict__ B,
             const float* __restrict__ bias, float* __restrict__ C,
             int M, int N, int K) {
    __shared__ float As[8][128];
    __shared__ float Bs[8][128];
    const int tid = threadIdx.x;
    const int bx = blockIdx.x * 128;        // col tile
    const int by = blockIdx.y * 128;        // row tile
    const int tx = (tid % 16) * 8;
    const int ty = (tid / 16) * 8;
    const int arow = tid >> 1;
    const int acol = (tid & 1) * 4;
    const int brow = tid >> 5;
    const int bcol = (tid & 31) * 4;

    float acc[8][8];
#pragma unroll
    for (int i = 0; i < 8; i++)
#pragma unroll
        for (int j = 0; j < 8; j++) acc[i][j] = 0.f;

    const bool arow_ok = (by + arow) < M;
    const float* Aptr = A + (size_t)(by + arow) * K + acol;
    const float* Bptr = B + (size_t)brow * N + bx + bcol;

    for (int k0 = 0; k0 < K; k0 += 8) {
        float4 av = make_float4(0.f, 0.f, 0.f, 0.f);
        if (arow_ok) av = *(const float4*)(Aptr + k0);
        float4 bv = *(const float4*)(Bptr + (size_t)k0 * N);
        As[acol + 0][arow] = av.x;
        As[acol + 1][arow] = av.y;
        As[acol + 2][arow] = av.z;
        As[acol + 3][arow] = av.w;
        *(float4*)&Bs[brow][bcol] = bv;
        __syncthreads();
#pragma unroll
        for (int kk = 0; kk < 8; kk++) {
            float ar[8], br[8];
            *(float4*)&ar[0] = *(const float4*)&As[kk][ty];
            *(float4*)&ar[4] = *(const float4*)&As[kk][ty + 4];
            *(float4*)&br[0] = *(const float4*)&Bs[kk][tx];
            *(float4*)&br[4] = *(const float4*)&Bs[kk][tx + 4];
#pragma unroll
            for (int i = 0; i < 8; i++)
#pragma unroll
                for (int j = 0; j < 8; j++)
                    acc[i][j] = fmaf(ar[i], br[j], acc[i][j]);
        }
        __syncthreads();
    }

    float bvals[8];
    if (HAS_BIAS) {
        *(float4*)&bvals[0] = *(const float4*)(bias + bx + tx);
        *(float4*)&bvals[4] = *(const float4*)(bias + bx + tx + 4);
    }
#pragma unroll
    for (int i = 0; i < 8; i++) {
        int r = by + ty + i;
        if (r < M) {
            float o[8];
#pragma unroll
            for (int j = 0; j < 8; j++) {
                float v = acc[i][j];
                if (HAS_BIAS) v += bvals[j];
                if (RELU) v = fmaxf(v, 0.f);
                o[j] = v;
            }
            *(float4*)(C + (size_t)r * N + bx + tx)     = *(float4*)&o[0];
            *(float4*)(C + (size_t)r * N + bx + tx + 4) = *(float4*)&o[4];
        }
    }
}

// ---------------------------------------------------------------------------
// launch
// ---------------------------------------------------------------------------
static inline int cdiv(int a, int b) { return (a + b - 1) / b; }

extern "C" void kernel_launch(void* const* d_in, const int* in_sizes, int n_in,
                              void* d_out, int out_size) {
    if (n_in < 11) return;
    const float* x  = (const float*)d_in[0];
    const int* ei1  = (const int*)d_in[1];
    const int* ei2  = (const int*)d_in[2];
    const float* W1 = (const float*)d_in[3];
    const float* b1 = (const float*)d_in[4];
    const float* W2 = (const float*)d_in[5];
    const float* b2 = (const float*)d_in[6];
    const float* W3 = (const float*)d_in[7];
    const float* b3 = (const float*)d_in[8];
    const float* W4 = (const float*)d_in[9];
    const float* b4 = (const float*)d_in[10];

    const int N  = in_sizes[0] / 512;
    const int E1 = in_sizes[1] / 2;
    const int E2 = in_sizes[2] / 2;
    const int* src1 = ei1;
    const int* dst1 = ei1 + E1;
    const int* src2 = ei2;
    const int* dst2 = ei2 + E2;

    float *b512a, *b512b, *b256a, *b256b, *inv1, *inv2;
    int *deg1, *deg2;
    cudaGetSymbolAddress((void**)&b512a, g_b512a);
    cudaGetSymbolAddress((void**)&b512b, g_b512b);
    cudaGetSymbolAddress((void**)&b256a, g_b256a);
    cudaGetSymbolAddress((void**)&b256b, g_b256b);
    cudaGetSymbolAddress((void**)&deg1,  g_deg1);
    cudaGetSymbolAddress((void**)&deg2,  g_deg2);
    cudaGetSymbolAddress((void**)&inv1,  g_inv1);
    cudaGetSymbolAddress((void**)&inv2,  g_inv2);

    float* out_z  = (float*)d_out;
    float* out_zg = out_z + (size_t)N * 256;

    const int rowTiles = cdiv(N, 128);

    // ---- degrees & normalization (re-zeroed each call) ----
    k_zero_deg<<<cdiv(N, 256), 256>>>(deg1, deg2, N);
    k_deg<<<cdiv(E1, 256), 256>>>(dst1, E1, deg1);
    k_deg<<<cdiv(E2, 256), 256>>>(dst2, E2, deg2);
    k_inv<<<cdiv(N, 256), 256>>>(deg1, deg2, inv1, inv2, N);

    // ---- Layer 1: h = x@W1 ; agg = A1n h + b1 ; relu (in place) ----
    k_sgemm<false, false><<<dim3(4, rowTiles), 256>>>(x, W1, nullptr, b512a, N, 512, 512);
    k_init_agg<512><<<cdiv(N * 128, 256), 256>>>(b512a, inv1, b1, b512b, N);
    k_scatter<512><<<cdiv(E1, 16), 256>>>(src1, dst1, inv1, b512a, b512b, E1);
    k_relu<<<cdiv(N * 128, 256), 256>>>(b512b, b512b, N * 128);

    // ---- Layer 2: h = z1@W2 ; agg = A1n h + b2 ; relu -> z (d_out) ----
    k_sgemm<false, false><<<dim3(2, rowTiles), 256>>>(b512b, W2, nullptr, b256a, N, 256, 512);
    k_init_agg<256><<<cdiv(N * 64, 256), 256>>>(b256a, inv1, b2, b256b, N);
    k_scatter<256><<<cdiv(E1, 32), 256>>>(src1, dst1, inv1, b256a, b256b, E1);
    k_relu<<<cdiv(N * 64, 256), 256>>>(b256b, out_z, N * 64);

    // ---- Layer 3 (aggregate-first): a = A2n z ; z3 = relu(a@W3 + b3) ----
    k_init_agg<256><<<cdiv(N * 64, 256), 256>>>(out_z, inv2, nullptr, b256a, N);
    k_scatter<256><<<cdiv(E2, 32), 256>>>(src2, dst2, inv2, out_z, b256a, E2);
    k_sgemm<true, true><<<dim3(4, rowTiles), 256>>>(b256a, W3, b3, b512a, N, 512, 256);

    // ---- Layer 4: h = z3@W4 ; agg = A2n h + b4 ; relu -> z_g ----
    k_sgemm<false, false><<<dim3(2, rowTiles), 256>>>(b512a, W4, nullptr, b256b, N, 256, 512);
    k_init_agg<256><<<cdiv(N * 64, 256), 256>>>(b256b, inv2, b4, b256a, N);
    k_scatter<256><<<cdiv(E2, 32), 256>>>(src2, dst2, inv2, b256b, b256a, E2);
    k_relu<<<cdiv(N * 64, 256), 256>>>(b256a, out_zg, N * 64);
}

// round 5
// speedup vs baseline: 1.8150x; 1.8150x over previous
#include <cuda_runtime.h>
#include <cuda_bf16.h>
#include <math.h>
#include <stdint.h>

// ---------------------------------------------------------------------------
// GCN encoder stack, mma.sync (baseline sm_100) edition:
//   z   = relu(A1n(relu(A1n(x W1)+b1) W2)+b2)
//   z_g = relu(A2n(relu((A2n z) W3 + b3) W4)+b4)   (layer3 reordered: A(zW)=(Az)W)
// GEMMs: bf16 hi/lo split (Ah*Bh + Ah*Bl + Al*Bh) on HMMA m16n8k16.
// NOTE: tcgen05/TMEM is unavailable — harness compiles for .target sm_100
// (no 'a' suffix), which rejects arch-accelerated instructions.
// ---------------------------------------------------------------------------

#define NMAX 50048

__device__ float g_b512a[(size_t)NMAX * 512];
__device__ float g_b512b[(size_t)NMAX * 512];
__device__ float g_b256a[(size_t)NMAX * 256];
__device__ float g_b256b[(size_t)NMAX * 256];
__device__ int   g_deg1[NMAX];
__device__ int   g_deg2[NMAX];
__device__ float g_inv1[NMAX];
__device__ float g_inv2[NMAX];

// bf16 split buffers for GEMM A operand (activations), [M,K] row-major
__device__ __nv_bfloat16 g_ah[(size_t)NMAX * 512];
__device__ __nv_bfloat16 g_al[(size_t)NMAX * 512];
// pre-transposed weights, K-major [N_out, K], bf16 hi/lo
__device__ __nv_bfloat16 g_wt1h[512 * 512], g_wt1l[512 * 512];
__device__ __nv_bfloat16 g_wt2h[256 * 512], g_wt2l[256 * 512];
__device__ __nv_bfloat16 g_wt3h[512 * 256], g_wt3l[512 * 256];
__device__ __nv_bfloat16 g_wt4h[256 * 512], g_wt4l[256 * 512];

// ---------------------------------------------------------------------------
// PTX helpers (all baseline sm_80+ features)
// ---------------------------------------------------------------------------
__device__ __forceinline__ uint32_t smem_u32(const void* p) {
    uint32_t a;
    asm("{ .reg .u64 t; cvta.to.shared.u64 t, %1; cvt.u32.u64 %0, t; }" : "=r"(a) : "l"(p));
    return a;
}

__device__ __forceinline__ void cp_async16(uint32_t dst, const void* src, bool pred) {
    int sz = pred ? 16 : 0;
    asm volatile("cp.async.cg.shared.global [%0], [%1], 16, %2;"
                 :: "r"(dst), "l"(src), "r"(sz) : "memory");
}
#define CP_COMMIT() asm volatile("cp.async.commit_group;" ::: "memory")
#define CP_WAIT(n)  asm volatile("cp.async.wait_group %0;" :: "n"(n) : "memory")

#define LDMATRIX_X4(r0, r1, r2, r3, addr) \
    asm volatile("ldmatrix.sync.aligned.m8n8.x4.shared.b16 {%0,%1,%2,%3}, [%4];" \
                 : "=r"(r0), "=r"(r1), "=r"(r2), "=r"(r3) : "r"(addr))

__device__ __forceinline__ void mma_bf16(float* c, const uint32_t* a, const uint32_t* b) {
    asm volatile(
        "mma.sync.aligned.m16n8k16.row.col.f32.bf16.bf16.f32 "
        "{%0,%1,%2,%3}, {%4,%5,%6,%7}, {%8,%9}, {%0,%1,%2,%3};"
        : "+f"(c[0]), "+f"(c[1]), "+f"(c[2]), "+f"(c[3])
        : "r"(a[0]), "r"(a[1]), "r"(a[2]), "r"(a[3]), "r"(b[0]), "r"(b[1]));
}

__device__ __forceinline__ void red_add_v4(float* addr, float4 v) {
    asm volatile("red.global.add.v4.f32 [%0], {%1, %2, %3, %4};"
                 :: "l"(addr), "f"(v.x), "f"(v.y), "f"(v.z), "f"(v.w) : "memory");
}

// ---------------------------------------------------------------------------
// degree / normalization
// ---------------------------------------------------------------------------
__global__ void k_zero_deg(int* d1, int* d2, int n) {
    int i = blockIdx.x * blockDim.x + threadIdx.x;
    if (i < n) { d1[i] = 0; d2[i] = 0; }
}
__global__ void k_deg(const int* __restrict__ dst, int E, int* deg) {
    int i = blockIdx.x * blockDim.x + threadIdx.x;
    if (i < E) atomicAdd(&deg[dst[i]], 1);
}
__global__ void k_inv(const int* __restrict__ d1, const int* __restrict__ d2,
                      float* i1, float* i2, int n) {
    int i = blockIdx.x * blockDim.x + threadIdx.x;
    if (i < n) {
        i1[i] = rsqrtf((float)d1[i] + 1.0f);
        i2[i] = rsqrtf((float)d2[i] + 1.0f);
    }
}

// ---------------------------------------------------------------------------
// fp32 -> bf16 hi/lo split (activations, row-major contiguous)
// ---------------------------------------------------------------------------
__global__ void k_cvt(const float* __restrict__ in, __nv_bfloat16* __restrict__ hi,
                      __nv_bfloat16* __restrict__ lo, int n4) {
    int i = blockIdx.x * blockDim.x + threadIdx.x;
    if (i >= n4) return;
    float4 v = ((const float4*)in)[i];
    __nv_bfloat16 hx = __float2bfloat16_rn(v.x), hy = __float2bfloat16_rn(v.y);
    __nv_bfloat16 hz = __float2bfloat16_rn(v.z), hw = __float2bfloat16_rn(v.w);
    __nv_bfloat16 lx = __float2bfloat16_rn(v.x - __bfloat162float(hx));
    __nv_bfloat16 ly = __float2bfloat16_rn(v.y - __bfloat162float(hy));
    __nv_bfloat16 lz = __float2bfloat16_rn(v.z - __bfloat162float(hz));
    __nv_bfloat16 lw = __float2bfloat16_rn(v.w - __bfloat162float(hw));
    __nv_bfloat162* H = (__nv_bfloat162*)hi;
    __nv_bfloat162* L = (__nv_bfloat162*)lo;
    H[2 * i]     = __nv_bfloat162(hx, hy);
    H[2 * i + 1] = __nv_bfloat162(hz, hw);
    L[2 * i]     = __nv_bfloat162(lx, ly);
    L[2 * i + 1] = __nv_bfloat162(lz, lw);
}

// weight transpose + split: W[K,N] -> Wt_hi/lo[N,K]
__global__ void k_wt(const float* __restrict__ W, __nv_bfloat16* __restrict__ th,
                     __nv_bfloat16* __restrict__ tl, int K, int N) {
    int idx = blockIdx.x * blockDim.x + threadIdx.x;
    if (idx >= N * K) return;
    int n = idx / K, k = idx - n * K;
    float w = W[(size_t)k * N + n];
    __nv_bfloat16 h = __float2bfloat16_rn(w);
    th[idx] = h;
    tl[idx] = __float2bfloat16_rn(w - __bfloat162float(h));
}

// ---------------------------------------------------------------------------
// agg init: agg[i,:] = h[i,:] * inv[i]^2 (+ bias)
// ---------------------------------------------------------------------------
template<int D>
__global__ void k_init_agg(const float* __restrict__ h, const float* __restrict__ inv,
                           const float* __restrict__ bias, float* __restrict__ agg, int n) {
    constexpr int C4 = D / 4;
    int idx = blockIdx.x * blockDim.x + threadIdx.x;
    if (idx >= n * C4) return;
    int row = idx / C4;
    int col = idx - row * C4;
    float s = inv[row]; s *= s;
    float4 v = ((const float4*)h)[idx];
    float4 o;
    if (bias) {
        float4 b = ((const float4*)bias)[col];
        o = make_float4(v.x * s + b.x, v.y * s + b.y, v.z * s + b.z, v.w * s + b.w);
    } else {
        o = make_float4(v.x * s, v.y * s, v.z * s, v.w * s);
    }
    ((float4*)agg)[idx] = o;
}

// ---------------------------------------------------------------------------
// edge scatter: agg[dst,:] += h[src,:] * inv[src]*inv[dst]
// ---------------------------------------------------------------------------
template<int D>
__global__ __launch_bounds__(256)
void k_scatter(const int* __restrict__ src, const int* __restrict__ dst,
               const float* __restrict__ inv, const float* __restrict__ h,
               float* agg, int E) {
    constexpr int TPE  = D / 4;
    constexpr int EPB  = 256 / TPE;
    constexpr int ITER = 8;
    int lane = threadIdx.x & (TPE - 1);
    int sub  = threadIdx.x / TPE;
    int base = blockIdx.x * (EPB * ITER) + sub;
#pragma unroll
    for (int it = 0; it < ITER; it++) {
        int e = base + it * EPB;
        if (e < E) {
            int s = src[e], d = dst[e];
            float c = inv[s] * inv[d];
            float4 v = *(const float4*)(h + (size_t)s * D + lane * 4);
            red_add_v4(agg + (size_t)d * D + lane * 4,
                       make_float4(v.x * c, v.y * c, v.z * c, v.w * c));
        }
    }
}

// ---------------------------------------------------------------------------
// relu copy
// ---------------------------------------------------------------------------
__global__ void k_relu(const float* __restrict__ in, float* __restrict__ out, int n4) {
    int i = blockIdx.x * blockDim.x + threadIdx.x;
    if (i >= n4) return;
    float4 v = ((const float4*)in)[i];
    v.x = fmaxf(v.x, 0.f); v.y = fmaxf(v.y, 0.f);
    v.z = fmaxf(v.z, 0.f); v.w = fmaxf(v.w, 0.f);
    ((float4*)out)[i] = v;
}

// ---------------------------------------------------------------------------
// HMMA GEMM: C[M,N] = A[M,K] * Wt[N,K]^T (+bias, +relu)
// A bf16 hi/lo [M,K]; Wt bf16 hi/lo [N,K] K-major.
// CTA 128x128, 512 thr (16 warps, warp tile 32x32), K chunks of 64,
// double-buffered smem (2 x 64KB) via cp.async, ldmatrix + mma.sync bf16.
// ---------------------------------------------------------------------------
#define STAGE_BYTES 65536
#define GEMM_SMEM_BYTES (2 * STAGE_BYTES)

template<bool HAS_BIAS, bool RELU>
__global__ __launch_bounds__(512)
void k_mmagemm(const __nv_bfloat16* __restrict__ Ah, const __nv_bfloat16* __restrict__ Al,
               const __nv_bfloat16* __restrict__ Bh, const __nv_bfloat16* __restrict__ Bl,
               const float* __restrict__ bias, float* __restrict__ C,
               int M, int N, int K) {
    extern __shared__ uint8_t smem[];
    const uint32_t sb = smem_u32(smem);

    const int tid  = threadIdx.x;
    const int wid  = tid >> 5;
    const int lane = tid & 31;
    const int wr   = wid >> 2;     // warp row 0..3  (rows wr*32..+31)
    const int wc   = wid & 3;      // warp col 0..3  (cols wc*32..+31)
    const int m0   = blockIdx.y * 128;
    const int n0   = blockIdx.x * 128;

    // per-thread load indexing (8 cp.async of 16B per chunk)
    const int lrow = tid >> 3;          // 0..63  (two j-steps cover 128 rows)
    const int lc16 = tid & 7;           // 16B column within 128B row

    // ldmatrix addressing components (fixed per thread)
    // A: matrices ordered m0-7/h0, m8-15/h0, m0-7/h1, m8-15/h1
    const int a_r = (lane & 7) + ((lane >> 3) & 1) * 8;   // row within 16
    const int a_h = (lane >> 4) & 1;                      // k half
    // B: matrices ordered n0-7/h0, n0-7/h1, n8-15/h0, n8-15/h1
    const int b_r = (lane & 7) + ((lane >> 4) & 1) * 8;
    const int b_h = (lane >> 3) & 1;

    float acc[2][4][4];
#pragma unroll
    for (int i = 0; i < 2; i++)
#pragma unroll
        for (int j = 0; j < 4; j++)
#pragma unroll
            for (int q = 0; q < 4; q++) acc[i][j][q] = 0.f;

    const int kIters = K >> 6;

    // ---- chunk loader: 4 tiles (Ah, Al, Bh, Bl), SW128 swizzle ----
    auto load_chunk = [&](int stage, int k0) {
        const uint32_t sbase = sb + stage * STAGE_BYTES;
#pragma unroll
        for (int j = 0; j < 2; j++) {
            const int row = lrow + j * 64;
            const int c16 = lc16;
            const uint32_t soff = (uint32_t)(row * 128 + ((c16 ^ (row & 7)) << 4));
            const bool aok = (m0 + row) < M;
            const int arow = aok ? (m0 + row) : (M - 1);
            const size_t ga = (size_t)arow * K + k0 + c16 * 8;
            cp_async16(sbase + soff,         Ah + ga, aok);
            cp_async16(sbase + 16384 + soff, Al + ga, aok);
            const size_t gb = (size_t)(n0 + row) * K + k0 + c16 * 8;
            cp_async16(sbase + 32768 + soff, Bh + gb, true);
            cp_async16(sbase + 49152 + soff, Bl + gb, true);
        }
        CP_COMMIT();
    };

    load_chunk(0, 0);

    int stage = 0;
    for (int it = 0; it < kIters; it++) {
        if (it + 1 < kIters) load_chunk(stage ^ 1, (it + 1) << 6);
        if (it + 1 < kIters) { CP_WAIT(1); } else { CP_WAIT(0); }
        __syncthreads();

        const uint32_t A_H = sb + stage * STAGE_BYTES;
        const uint32_t A_L = A_H + 16384;
        const uint32_t B_H = A_H + 32768;
        const uint32_t B_L = A_H + 49152;

#pragma unroll
        for (int ks = 0; ks < 4; ks++) {
            uint32_t af_h[2][4], af_l[2][4];
#pragma unroll
            for (int am = 0; am < 2; am++) {
                const int row = wr * 32 + am * 16 + a_r;
                const int c16 = ks * 2 + a_h;
                const uint32_t off = (uint32_t)(row * 128 + ((c16 ^ (row & 7)) << 4));
                LDMATRIX_X4(af_h[am][0], af_h[am][1], af_h[am][2], af_h[am][3], A_H + off);
                LDMATRIX_X4(af_l[am][0], af_l[am][1], af_l[am][2], af_l[am][3], A_L + off);
            }
            uint32_t bf_h[4][2], bf_l[4][2];
#pragma unroll
            for (int bp = 0; bp < 2; bp++) {
                const int row = wc * 32 + bp * 16 + b_r;
                const int c16 = ks * 2 + b_h;
                const uint32_t off = (uint32_t)(row * 128 + ((c16 ^ (row & 7)) << 4));
                uint32_t r0, r1, r2, r3;
                LDMATRIX_X4(r0, r1, r2, r3, B_H + off);
                bf_h[bp * 2][0] = r0; bf_h[bp * 2][1] = r1;
                bf_h[bp * 2 + 1][0] = r2; bf_h[bp * 2 + 1][1] = r3;
                LDMATRIX_X4(r0, r1, r2, r3, B_L + off);
                bf_l[bp * 2][0] = r0; bf_l[bp * 2][1] = r1;
                bf_l[bp * 2 + 1][0] = r2; bf_l[bp * 2 + 1][1] = r3;
            }
#pragma unroll
            for (int am = 0; am < 2; am++)
#pragma unroll
                for (int bn = 0; bn < 4; bn++) {
                    mma_bf16(acc[am][bn], af_h[am], bf_h[bn]);
                    mma_bf16(acc[am][bn], af_h[am], bf_l[bn]);
                    mma_bf16(acc[am][bn], af_l[am], bf_h[bn]);
                }
        }
        __syncthreads();
        stage ^= 1;
    }

    // ---- epilogue ----
    const int r_base = m0 + wr * 32 + (lane >> 2);
    const int c_base = n0 + wc * 32 + (lane & 3) * 2;
#pragma unroll
    for (int am = 0; am < 2; am++) {
#pragma unroll
        for (int bn = 0; bn < 4; bn++) {
            const int col = c_base + bn * 8;
            float bx = 0.f, by = 0.f;
            if (HAS_BIAS) { bx = __ldg(bias + col); by = __ldg(bias + col + 1); }
#pragma unroll
            for (int h = 0; h < 2; h++) {
                const int row = r_base + am * 16 + h * 8;
                if (row < M) {
                    float v0 = acc[am][bn][h * 2]     + bx;
                    float v1 = acc[am][bn][h * 2 + 1] + by;
                    if (RELU) { v0 = fmaxf(v0, 0.f); v1 = fmaxf(v1, 0.f); }
                    float2 o = make_float2(v0, v1);
                    *(float2*)(C + (size_t)row * N + col) = o;
                }
            }
        }
    }
}

// ---------------------------------------------------------------------------
// launch
// ---------------------------------------------------------------------------
static inline int cdiv(int a, int b) { return (a + b - 1) / b; }

extern "C" void kernel_launch(void* const* d_in, const int* in_sizes, int n_in,
                              void* d_out, int out_size) {
    if (n_in < 11) return;
    const float* x  = (const float*)d_in[0];
    const int* ei1  = (const int*)d_in[1];
    const int* ei2  = (const int*)d_in[2];
    const float* W1 = (const float*)d_in[3];
    const float* b1 = (const float*)d_in[4];
    const float* W2 = (const float*)d_in[5];
    const float* b2 = (const float*)d_in[6];
    const float* W3 = (const float*)d_in[7];
    const float* b3 = (const float*)d_in[8];
    const float* W4 = (const float*)d_in[9];
    const float* b4 = (const float*)d_in[10];

    const int N  = in_sizes[0] / 512;
    const int E1 = in_sizes[1] / 2;
    const int E2 = in_sizes[2] / 2;
    const int* src1 = ei1;
    const int* dst1 = ei1 + E1;
    const int* src2 = ei2;
    const int* dst2 = ei2 + E2;

    float *b512a, *b512b, *b256a, *b256b, *inv1, *inv2;
    int *deg1, *deg2;
    __nv_bfloat16 *ah, *al, *wt1h, *wt1l, *wt2h, *wt2l, *wt3h, *wt3l, *wt4h, *wt4l;
    cudaGetSymbolAddress((void**)&b512a, g_b512a);
    cudaGetSymbolAddress((void**)&b512b, g_b512b);
    cudaGetSymbolAddress((void**)&b256a, g_b256a);
    cudaGetSymbolAddress((void**)&b256b, g_b256b);
    cudaGetSymbolAddress((void**)&deg1,  g_deg1);
    cudaGetSymbolAddress((void**)&deg2,  g_deg2);
    cudaGetSymbolAddress((void**)&inv1,  g_inv1);
    cudaGetSymbolAddress((void**)&inv2,  g_inv2);
    cudaGetSymbolAddress((void**)&ah,    g_ah);
    cudaGetSymbolAddress((void**)&al,    g_al);
    cudaGetSymbolAddress((void**)&wt1h,  g_wt1h);  cudaGetSymbolAddress((void**)&wt1l, g_wt1l);
    cudaGetSymbolAddress((void**)&wt2h,  g_wt2h);  cudaGetSymbolAddress((void**)&wt2l, g_wt2l);
    cudaGetSymbolAddress((void**)&wt3h,  g_wt3h);  cudaGetSymbolAddress((void**)&wt3l, g_wt3l);
    cudaGetSymbolAddress((void**)&wt4h,  g_wt4h);  cudaGetSymbolAddress((void**)&wt4l, g_wt4l);

    cudaFuncSetAttribute(k_mmagemm<false, false>,
                         cudaFuncAttributeMaxDynamicSharedMemorySize, GEMM_SMEM_BYTES);
    cudaFuncSetAttribute(k_mmagemm<true, true>,
                         cudaFuncAttributeMaxDynamicSharedMemorySize, GEMM_SMEM_BYTES);

    float* out_z  = (float*)d_out;
    float* out_zg = out_z + (size_t)N * 256;
    const int rowT = cdiv(N, 128);

    // ---- prep: weight transpose+split, degrees & normalization ----
    k_wt<<<cdiv(512 * 512, 256), 256>>>(W1, wt1h, wt1l, 512, 512);
    k_wt<<<cdiv(256 * 512, 256), 256>>>(W2, wt2h, wt2l, 512, 256);
    k_wt<<<cdiv(512 * 256, 256), 256>>>(W3, wt3h, wt3l, 256, 512);
    k_wt<<<cdiv(256 * 512, 256), 256>>>(W4, wt4h, wt4l, 512, 256);
    k_zero_deg<<<cdiv(N, 256), 256>>>(deg1, deg2, N);
    k_deg<<<cdiv(E1, 256), 256>>>(dst1, E1, deg1);
    k_deg<<<cdiv(E2, 256), 256>>>(dst2, E2, deg2);
    k_inv<<<cdiv(N, 256), 256>>>(deg1, deg2, inv1, inv2, N);

    // ---- Layer 1: h = x@W1 ; agg = A1n h + b1 ; relu (in place) ----
    k_cvt<<<cdiv(N * 128, 256), 256>>>(x, ah, al, N * 128);
    k_mmagemm<false, false><<<dim3(4, rowT), 512, GEMM_SMEM_BYTES>>>(
        ah, al, wt1h, wt1l, nullptr, b512a, N, 512, 512);
    k_init_agg<512><<<cdiv(N * 128, 256), 256>>>(b512a, inv1, b1, b512b, N);
    k_scatter<512><<<cdiv(E1, 16), 256>>>(src1, dst1, inv1, b512a, b512b, E1);
    k_relu<<<cdiv(N * 128, 256), 256>>>(b512b, b512b, N * 128);

    // ---- Layer 2: h = z1@W2 ; agg = A1n h + b2 ; relu -> z (d_out) ----
    k_cvt<<<cdiv(N * 128, 256), 256>>>(b512b, ah, al, N * 128);
    k_mmagemm<false, false><<<dim3(2, rowT), 512, GEMM_SMEM_BYTES>>>(
        ah, al, wt2h, wt2l, nullptr, b256a, N, 256, 512);
    k_init_agg<256><<<cdiv(N * 64, 256), 256>>>(b256a, inv1, b2, b256b, N);
    k_scatter<256><<<cdiv(E1, 32), 256>>>(src1, dst1, inv1, b256a, b256b, E1);
    k_relu<<<cdiv(N * 64, 256), 256>>>(b256b, out_z, N * 64);

    // ---- Layer 3 (aggregate-first): a = A2n z ; z3 = relu(a@W3 + b3) ----
    k_init_agg<256><<<cdiv(N * 64, 256), 256>>>(out_z, inv2, nullptr, b256a, N);
    k_scatter<256><<<cdiv(E2, 32), 256>>>(src2, dst2, inv2, out_z, b256a, E2);
    k_cvt<<<cdiv(N * 64, 256), 256>>>(b256a, ah, al, N * 64);
    k_mmagemm<true, true><<<dim3(4, rowT), 512, GEMM_SMEM_BYTES>>>(
        ah, al, wt3h, wt3l, b3, b512a, N, 512, 256);

    // ---- Layer 4: h = z3@W4 ; agg = A2n h + b4 ; relu -> z_g ----
    k_cvt<<<cdiv(N * 128, 256), 256>>>(b512a, ah, al, N * 128);
    k_mmagemm<false, false><<<dim3(2, rowT), 512, GEMM_SMEM_BYTES>>>(
        ah, al, wt4h, wt4l, nullptr, b256b, N, 256, 512);
    k_init_agg<256><<<cdiv(N * 64, 256), 256>>>(b256b, inv2, b4, b256a, N);
    k_scatter<256><<<cdiv(E2, 32), 256>>>(src2, dst2, inv2, b256b, b256a, E2);
    k_relu<<<cdiv(N * 64, 256), 256>>>(b256a, out_zg, N * 64);
}

// round 6
// speedup vs baseline: 1.9201x; 1.0579x over previous
#include <cuda_runtime.h>
#include <cuda_bf16.h>
#include <math.h>
#include <stdint.h>

// ---------------------------------------------------------------------------
// GCN encoder stack, mma.sync (baseline sm_100) edition, fused-epilogue round:
//   z   = relu(A1n(relu(A1n(x W1)+b1) W2)+b2)
//   z_g = relu(A2n(relu((A2n z) W3 + b3) W4)+b4)   (layer3 reordered: A(zW)=(Az)W)
// GEMMs: bf16 hi/lo split (Ah*Bh + Ah*Bl + Al*Bh) on HMMA m16n8k16.
// Epilogues fused: h+agg-init dual store (L1/L2/L4), relu+bf16-split (L3).
// ---------------------------------------------------------------------------

#define NMAX 50048

__device__ float g_b512a[(size_t)NMAX * 512];
__device__ float g_b512b[(size_t)NMAX * 512];
__device__ float g_b256a[(size_t)NMAX * 256];
__device__ float g_b256b[(size_t)NMAX * 256];
__device__ int   g_deg1[NMAX];
__device__ int   g_deg2[NMAX];
__device__ float g_inv1[NMAX];
__device__ float g_inv2[NMAX];

// bf16 split buffers for GEMM A operands
__device__ __nv_bfloat16 g_ah[(size_t)NMAX * 512];
__device__ __nv_bfloat16 g_al[(size_t)NMAX * 512];
__device__ __nv_bfloat16 g_ah2[(size_t)NMAX * 512];
__device__ __nv_bfloat16 g_al2[(size_t)NMAX * 512];
// pre-transposed weights, K-major [N_out, K], bf16 hi/lo
__device__ __nv_bfloat16 g_wt1h[512 * 512], g_wt1l[512 * 512];
__device__ __nv_bfloat16 g_wt2h[256 * 512], g_wt2l[256 * 512];
__device__ __nv_bfloat16 g_wt3h[512 * 256], g_wt3l[512 * 256];
__device__ __nv_bfloat16 g_wt4h[256 * 512], g_wt4l[256 * 512];

// ---------------------------------------------------------------------------
// PTX helpers (all baseline sm_80+ features)
// ---------------------------------------------------------------------------
__device__ __forceinline__ uint32_t smem_u32(const void* p) {
    uint32_t a;
    asm("{ .reg .u64 t; cvta.to.shared.u64 t, %1; cvt.u32.u64 %0, t; }" : "=r"(a) : "l"(p));
    return a;
}

__device__ __forceinline__ void cp_async16(uint32_t dst, const void* src, bool pred) {
    int sz = pred ? 16 : 0;
    asm volatile("cp.async.cg.shared.global [%0], [%1], 16, %2;"
                 :: "r"(dst), "l"(src), "r"(sz) : "memory");
}
#define CP_COMMIT() asm volatile("cp.async.commit_group;" ::: "memory")
#define CP_WAIT(n)  asm volatile("cp.async.wait_group %0;" :: "n"(n) : "memory")

#define LDMATRIX_X4(r0, r1, r2, r3, addr) \
    asm volatile("ldmatrix.sync.aligned.m8n8.x4.shared.b16 {%0,%1,%2,%3}, [%4];" \
                 : "=r"(r0), "=r"(r1), "=r"(r2), "=r"(r3) : "r"(addr))

__device__ __forceinline__ void mma_bf16(float* c, const uint32_t* a, const uint32_t* b) {
    asm volatile(
        "mma.sync.aligned.m16n8k16.row.col.f32.bf16.bf16.f32 "
        "{%0,%1,%2,%3}, {%4,%5,%6,%7}, {%8,%9}, {%0,%1,%2,%3};"
        : "+f"(c[0]), "+f"(c[1]), "+f"(c[2]), "+f"(c[3])
        : "r"(a[0]), "r"(a[1]), "r"(a[2]), "r"(a[3]), "r"(b[0]), "r"(b[1]));
}

__device__ __forceinline__ void red_add_v4(float* addr, float4 v) {
    asm volatile("red.global.add.v4.f32 [%0], {%1, %2, %3, %4};"
                 :: "l"(addr), "f"(v.x), "f"(v.y), "f"(v.z), "f"(v.w) : "memory");
}

// ---------------------------------------------------------------------------
// degree / normalization
// ---------------------------------------------------------------------------
__global__ void k_zero_deg(int* d1, int* d2, int n) {
    int i = blockIdx.x * blockDim.x + threadIdx.x;
    if (i < n) { d1[i] = 0; d2[i] = 0; }
}
__global__ void k_deg(const int* __restrict__ dst, int E, int* deg) {
    int i = blockIdx.x * blockDim.x + threadIdx.x;
    if (i < E) atomicAdd(&deg[dst[i]], 1);
}
__global__ void k_inv(const int* __restrict__ d1, const int* __restrict__ d2,
                      float* i1, float* i2, int n) {
    int i = blockIdx.x * blockDim.x + threadIdx.x;
    if (i < n) {
        i1[i] = rsqrtf((float)d1[i] + 1.0f);
        i2[i] = rsqrtf((float)d2[i] + 1.0f);
    }
}

// ---------------------------------------------------------------------------
// fp32 -> bf16 hi/lo split, optional relu (row-major contiguous)
// ---------------------------------------------------------------------------
template<bool RELU>
__global__ void k_cvt(const float* __restrict__ in, __nv_bfloat16* __restrict__ hi,
                      __nv_bfloat16* __restrict__ lo, int n4) {
    int i = blockIdx.x * blockDim.x + threadIdx.x;
    if (i >= n4) return;
    float4 v = ((const float4*)in)[i];
    if (RELU) {
        v.x = fmaxf(v.x, 0.f); v.y = fmaxf(v.y, 0.f);
        v.z = fmaxf(v.z, 0.f); v.w = fmaxf(v.w, 0.f);
    }
    __nv_bfloat16 hx = __float2bfloat16_rn(v.x), hy = __float2bfloat16_rn(v.y);
    __nv_bfloat16 hz = __float2bfloat16_rn(v.z), hw = __float2bfloat16_rn(v.w);
    __nv_bfloat16 lx = __float2bfloat16_rn(v.x - __bfloat162float(hx));
    __nv_bfloat16 ly = __float2bfloat16_rn(v.y - __bfloat162float(hy));
    __nv_bfloat16 lz = __float2bfloat16_rn(v.z - __bfloat162float(hz));
    __nv_bfloat16 lw = __float2bfloat16_rn(v.w - __bfloat162float(hw));
    __nv_bfloat162* H = (__nv_bfloat162*)hi;
    __nv_bfloat162* L = (__nv_bfloat162*)lo;
    H[2 * i]     = __nv_bfloat162(hx, hy);
    H[2 * i + 1] = __nv_bfloat162(hz, hw);
    L[2 * i]     = __nv_bfloat162(lx, ly);
    L[2 * i + 1] = __nv_bfloat162(lz, lw);
}

// weight transpose + split: W[K,N] -> Wt_hi/lo[N,K]
__global__ void k_wt(const float* __restrict__ W, __nv_bfloat16* __restrict__ th,
                     __nv_bfloat16* __restrict__ tl, int K, int N) {
    int idx = blockIdx.x * blockDim.x + threadIdx.x;
    if (idx >= N * K) return;
    int n = idx / K, k = idx - n * K;
    float w = W[(size_t)k * N + n];
    __nv_bfloat16 h = __float2bfloat16_rn(w);
    th[idx] = h;
    tl[idx] = __float2bfloat16_rn(w - __bfloat162float(h));
}

// ---------------------------------------------------------------------------
// fused: out_relu = relu(in); out_agg = relu(in) * inv2[row]^2   (D=256)
// ---------------------------------------------------------------------------
__global__ void k_relu_out_agg(const float* __restrict__ in, const float* __restrict__ inv,
                               float* __restrict__ out_relu, float* __restrict__ out_agg,
                               int n) {
    int idx = blockIdx.x * blockDim.x + threadIdx.x;
    if (idx >= n * 64) return;
    int row = idx >> 6;
    float s = __ldg(inv + row); s *= s;
    float4 v = ((const float4*)in)[idx];
    v.x = fmaxf(v.x, 0.f); v.y = fmaxf(v.y, 0.f);
    v.z = fmaxf(v.z, 0.f); v.w = fmaxf(v.w, 0.f);
    ((float4*)out_relu)[idx] = v;
    ((float4*)out_agg)[idx] = make_float4(v.x * s, v.y * s, v.z * s, v.w * s);
}

// ---------------------------------------------------------------------------
// edge scatter: agg[dst,:] += h[src,:] * inv[src]*inv[dst]
// ---------------------------------------------------------------------------
template<int D>
__global__ __launch_bounds__(256)
void k_scatter(const int* __restrict__ src, const int* __restrict__ dst,
               const float* __restrict__ inv, const float* __restrict__ h,
               float* agg, int E) {
    constexpr int TPE  = D / 4;
    constexpr int EPB  = 256 / TPE;
    constexpr int ITER = 8;
    int lane = threadIdx.x & (TPE - 1);
    int sub  = threadIdx.x / TPE;
    int base = blockIdx.x * (EPB * ITER) + sub;
#pragma unroll
    for (int it = 0; it < ITER; it++) {
        int e = base + it * EPB;
        if (e < E) {
            int s = src[e], d = dst[e];
            float c = inv[s] * inv[d];
            float4 v = *(const float4*)(h + (size_t)s * D + lane * 4);
            red_add_v4(agg + (size_t)d * D + lane * 4,
                       make_float4(v.x * c, v.y * c, v.z * c, v.w * c));
        }
    }
}

// ---------------------------------------------------------------------------
// relu copy (final output)
// ---------------------------------------------------------------------------
__global__ void k_relu(const float* __restrict__ in, float* __restrict__ out, int n4) {
    int i = blockIdx.x * blockDim.x + threadIdx.x;
    if (i >= n4) return;
    float4 v = ((const float4*)in)[i];
    v.x = fmaxf(v.x, 0.f); v.y = fmaxf(v.y, 0.f);
    v.z = fmaxf(v.z, 0.f); v.w = fmaxf(v.w, 0.f);
    ((float4*)out)[i] = v;
}

// ---------------------------------------------------------------------------
// HMMA GEMM: acc[M,N] = A[M,K] * Wt[N,K]^T, then fused epilogue:
//   MODE 0 (H_AGG):    C0[row,col] = acc ; C1[row,col] = acc*inv[row]^2 + bias[col]
//   MODE 1 (RELUSPLIT): v = relu(acc + bias[col]); C0 = bf16_hi(v), C1 = bf16_lo(v)
// CTA 128x128, 512 thr (16 warps, warp tile 32x32), K chunks of 64,
// double-buffered smem via cp.async, ldmatrix + mma.sync bf16 3-way split.
// ---------------------------------------------------------------------------
#define STAGE_BYTES 65536
#define GEMM_SMEM_BYTES (2 * STAGE_BYTES)

template<int MODE>
__global__ __launch_bounds__(512)
void k_mmagemm(const __nv_bfloat16* __restrict__ Ah, const __nv_bfloat16* __restrict__ Al,
               const __nv_bfloat16* __restrict__ Bh, const __nv_bfloat16* __restrict__ Bl,
               const float* __restrict__ bias, const float* __restrict__ inv,
               void* __restrict__ C0v, void* __restrict__ C1v,
               int M, int N, int K) {
    extern __shared__ uint8_t smem[];
    const uint32_t sb = smem_u32(smem);

    const int tid  = threadIdx.x;
    const int wid  = tid >> 5;
    const int lane = tid & 31;
    const int wr   = wid >> 2;
    const int wc   = wid & 3;
    const int m0   = blockIdx.y * 128;
    const int n0   = blockIdx.x * 128;

    const int lrow = tid >> 3;
    const int lc16 = tid & 7;

    const int a_r = (lane & 7) + ((lane >> 3) & 1) * 8;
    const int a_h = (lane >> 4) & 1;
    const int b_r = (lane & 7) + ((lane >> 4) & 1) * 8;
    const int b_h = (lane >> 3) & 1;

    float acc[2][4][4];
#pragma unroll
    for (int i = 0; i < 2; i++)
#pragma unroll
        for (int j = 0; j < 4; j++)
#pragma unroll
            for (int q = 0; q < 4; q++) acc[i][j][q] = 0.f;

    const int kIters = K >> 6;

    auto load_chunk = [&](int stage, int k0) {
        const uint32_t sbase = sb + stage * STAGE_BYTES;
#pragma unroll
        for (int j = 0; j < 2; j++) {
            const int row = lrow + j * 64;
            const int c16 = lc16;
            const uint32_t soff = (uint32_t)(row * 128 + ((c16 ^ (row & 7)) << 4));
            const bool aok = (m0 + row) < M;
            const int arow = aok ? (m0 + row) : (M - 1);
            const size_t ga = (size_t)arow * K + k0 + c16 * 8;
            cp_async16(sbase + soff,         Ah + ga, aok);
            cp_async16(sbase + 16384 + soff, Al + ga, aok);
            const size_t gb = (size_t)(n0 + row) * K + k0 + c16 * 8;
            cp_async16(sbase + 32768 + soff, Bh + gb, true);
            cp_async16(sbase + 49152 + soff, Bl + gb, true);
        }
        CP_COMMIT();
    };

    load_chunk(0, 0);

    int stage = 0;
    for (int it = 0; it < kIters; it++) {
        if (it + 1 < kIters) load_chunk(stage ^ 1, (it + 1) << 6);
        if (it + 1 < kIters) { CP_WAIT(1); } else { CP_WAIT(0); }
        __syncthreads();

        const uint32_t A_H = sb + stage * STAGE_BYTES;
        const uint32_t A_L = A_H + 16384;
        const uint32_t B_H = A_H + 32768;
        const uint32_t B_L = A_H + 49152;

#pragma unroll
        for (int ks = 0; ks < 4; ks++) {
            uint32_t af_h[2][4], af_l[2][4];
#pragma unroll
            for (int am = 0; am < 2; am++) {
                const int row = wr * 32 + am * 16 + a_r;
                const int c16 = ks * 2 + a_h;
                const uint32_t off = (uint32_t)(row * 128 + ((c16 ^ (row & 7)) << 4));
                LDMATRIX_X4(af_h[am][0], af_h[am][1], af_h[am][2], af_h[am][3], A_H + off);
                LDMATRIX_X4(af_l[am][0], af_l[am][1], af_l[am][2], af_l[am][3], A_L + off);
            }
            uint32_t bf_h[4][2], bf_l[4][2];
#pragma unroll
            for (int bp = 0; bp < 2; bp++) {
                const int row = wc * 32 + bp * 16 + b_r;
                const int c16 = ks * 2 + b_h;
                const uint32_t off = (uint32_t)(row * 128 + ((c16 ^ (row & 7)) << 4));
                uint32_t r0, r1, r2, r3;
                LDMATRIX_X4(r0, r1, r2, r3, B_H + off);
                bf_h[bp * 2][0] = r0; bf_h[bp * 2][1] = r1;
                bf_h[bp * 2 + 1][0] = r2; bf_h[bp * 2 + 1][1] = r3;
                LDMATRIX_X4(r0, r1, r2, r3, B_L + off);
                bf_l[bp * 2][0] = r0; bf_l[bp * 2][1] = r1;
                bf_l[bp * 2 + 1][0] = r2; bf_l[bp * 2 + 1][1] = r3;
            }
#pragma unroll
            for (int am = 0; am < 2; am++)
#pragma unroll
                for (int bn = 0; bn < 4; bn++) {
                    mma_bf16(acc[am][bn], af_h[am], bf_h[bn]);
                    mma_bf16(acc[am][bn], af_h[am], bf_l[bn]);
                    mma_bf16(acc[am][bn], af_l[am], bf_h[bn]);
                }
        }
        __syncthreads();
        stage ^= 1;
    }

    // ---- fused epilogue ----
    const int r_base = m0 + wr * 32 + (lane >> 2);
    const int c_base = n0 + wc * 32 + (lane & 3) * 2;
#pragma unroll
    for (int am = 0; am < 2; am++) {
#pragma unroll
        for (int bn = 0; bn < 4; bn++) {
            const int col = c_base + bn * 8;
            const float bx = __ldg(bias + col), by = __ldg(bias + col + 1);
#pragma unroll
            for (int h = 0; h < 2; h++) {
                const int row = r_base + am * 16 + h * 8;
                if (row < M) {
                    float v0 = acc[am][bn][h * 2];
                    float v1 = acc[am][bn][h * 2 + 1];
                    if (MODE == 0) {
                        // h out + agg-init out
                        float* Ch = (float*)C0v;
                        float* Cg = (float*)C1v;
                        float s = __ldg(inv + row); s *= s;
                        *(float2*)(Ch + (size_t)row * N + col) = make_float2(v0, v1);
                        *(float2*)(Cg + (size_t)row * N + col) =
                            make_float2(v0 * s + bx, v1 * s + by);
                    } else {
                        // relu + bf16 hi/lo split out
                        float u0 = fmaxf(v0 + bx, 0.f);
                        float u1 = fmaxf(v1 + by, 0.f);
                        __nv_bfloat16 h0 = __float2bfloat16_rn(u0);
                        __nv_bfloat16 h1 = __float2bfloat16_rn(u1);
                        __nv_bfloat16 l0 = __float2bfloat16_rn(u0 - __bfloat162float(h0));
                        __nv_bfloat16 l1 = __float2bfloat16_rn(u1 - __bfloat162float(h1));
                        __nv_bfloat16* CH = (__nv_bfloat16*)C0v;
                        __nv_bfloat16* CL = (__nv_bfloat16*)C1v;
                        *(__nv_bfloat162*)(CH + (size_t)row * N + col) = __nv_bfloat162(h0, h1);
                        *(__nv_bfloat162*)(CL + (size_t)row * N + col) = __nv_bfloat162(l0, l1);
                    }
                }
            }
        }
    }
}

// ---------------------------------------------------------------------------
// launch
// ---------------------------------------------------------------------------
static inline int cdiv(int a, int b) { return (a + b - 1) / b; }

extern "C" void kernel_launch(void* const* d_in, const int* in_sizes, int n_in,
                              void* d_out, int out_size) {
    if (n_in < 11) return;
    const float* x  = (const float*)d_in[0];
    const int* ei1  = (const int*)d_in[1];
    const int* ei2  = (const int*)d_in[2];
    const float* W1 = (const float*)d_in[3];
    const float* b1 = (const float*)d_in[4];
    const float* W2 = (const float*)d_in[5];
    const float* b2 = (const float*)d_in[6];
    const float* W3 = (const float*)d_in[7];
    const float* b3 = (const float*)d_in[8];
    const float* W4 = (const float*)d_in[9];
    const float* b4 = (const float*)d_in[10];

    const int N  = in_sizes[0] / 512;
    const int E1 = in_sizes[1] / 2;
    const int E2 = in_sizes[2] / 2;
    const int* src1 = ei1;
    const int* dst1 = ei1 + E1;
    const int* src2 = ei2;
    const int* dst2 = ei2 + E2;

    float *b512a, *b512b, *b256a, *b256b, *inv1, *inv2;
    int *deg1, *deg2;
    __nv_bfloat16 *ah, *al, *ah2, *al2;
    __nv_bfloat16 *wt1h, *wt1l, *wt2h, *wt2l, *wt3h, *wt3l, *wt4h, *wt4l;
    cudaGetSymbolAddress((void**)&b512a, g_b512a);
    cudaGetSymbolAddress((void**)&b512b, g_b512b);
    cudaGetSymbolAddress((void**)&b256a, g_b256a);
    cudaGetSymbolAddress((void**)&b256b, g_b256b);
    cudaGetSymbolAddress((void**)&deg1,  g_deg1);
    cudaGetSymbolAddress((void**)&deg2,  g_deg2);
    cudaGetSymbolAddress((void**)&inv1,  g_inv1);
    cudaGetSymbolAddress((void**)&inv2,  g_inv2);
    cudaGetSymbolAddress((void**)&ah,    g_ah);
    cudaGetSymbolAddress((void**)&al,    g_al);
    cudaGetSymbolAddress((void**)&ah2,   g_ah2);
    cudaGetSymbolAddress((void**)&al2,   g_al2);
    cudaGetSymbolAddress((void**)&wt1h,  g_wt1h);  cudaGetSymbolAddress((void**)&wt1l, g_wt1l);
    cudaGetSymbolAddress((void**)&wt2h,  g_wt2h);  cudaGetSymbolAddress((void**)&wt2l, g_wt2l);
    cudaGetSymbolAddress((void**)&wt3h,  g_wt3h);  cudaGetSymbolAddress((void**)&wt3l, g_wt3l);
    cudaGetSymbolAddress((void**)&wt4h,  g_wt4h);  cudaGetSymbolAddress((void**)&wt4l, g_wt4l);

    cudaFuncSetAttribute(k_mmagemm<0>,
                         cudaFuncAttributeMaxDynamicSharedMemorySize, GEMM_SMEM_BYTES);
    cudaFuncSetAttribute(k_mmagemm<1>,
                         cudaFuncAttributeMaxDynamicSharedMemorySize, GEMM_SMEM_BYTES);

    float* out_z  = (float*)d_out;
    float* out_zg = out_z + (size_t)N * 256;
    const int rowT = cdiv(N, 128);

    // ---- prep: weight transpose+split, degrees & normalization ----
    k_wt<<<cdiv(512 * 512, 256), 256>>>(W1, wt1h, wt1l, 512, 512);
    k_wt<<<cdiv(256 * 512, 256), 256>>>(W2, wt2h, wt2l, 512, 256);
    k_wt<<<cdiv(512 * 256, 256), 256>>>(W3, wt3h, wt3l, 256, 512);
    k_wt<<<cdiv(256 * 512, 256), 256>>>(W4, wt4h, wt4l, 512, 256);
    k_zero_deg<<<cdiv(N, 256), 256>>>(deg1, deg2, N);
    k_deg<<<cdiv(E1, 256), 256>>>(dst1, E1, deg1);
    k_deg<<<cdiv(E2, 256), 256>>>(dst2, E2, deg2);
    k_inv<<<cdiv(N, 256), 256>>>(deg1, deg2, inv1, inv2, N);

    // ---- Layer 1: h=x@W1 (epi: h->b512a, h*inv1^2+b1->b512b); scatter; relu+cvt ----
    k_cvt<false><<<cdiv(N * 128, 256), 256>>>(x, ah, al, N * 128);
    k_mmagemm<0><<<dim3(4, rowT), 512, GEMM_SMEM_BYTES>>>(
        ah, al, wt1h, wt1l, b1, inv1, b512a, b512b, N, 512, 512);
    k_scatter<512><<<cdiv(E1, 16), 256>>>(src1, dst1, inv1, b512a, b512b, E1);
    k_cvt<true><<<cdiv(N * 128, 256), 256>>>(b512b, ah, al, N * 128);

    // ---- Layer 2: h=z1@W2 (epi: h->b256a, init->b256b); scatter; relu->out_z + agg-init for L3 ----
    k_mmagemm<0><<<dim3(2, rowT), 512, GEMM_SMEM_BYTES>>>(
        ah, al, wt2h, wt2l, b2, inv1, b256a, b256b, N, 256, 512);
    k_scatter<256><<<cdiv(E1, 32), 256>>>(src1, dst1, inv1, b256a, b256b, E1);
    k_relu_out_agg<<<cdiv(N * 64, 256), 256>>>(b256b, inv2, out_z, b256a, N);

    // ---- Layer 3 (aggregate-first): scatter A2n z; GEMM3 (epi: relu+split -> ah2/al2) ----
    k_scatter<256><<<cdiv(E2, 32), 256>>>(src2, dst2, inv2, out_z, b256a, E2);
    k_cvt<false><<<cdiv(N * 64, 256), 256>>>(b256a, ah, al, N * 64);
    k_mmagemm<1><<<dim3(4, rowT), 512, GEMM_SMEM_BYTES>>>(
        ah, al, wt3h, wt3l, b3, inv2, ah2, al2, N, 512, 256);

    // ---- Layer 4: h=z3@W4 (epi: h->b256b, init->b256a); scatter; relu -> out_zg ----
    k_mmagemm<0><<<dim3(2, rowT), 512, GEMM_SMEM_BYTES>>>(
        ah2, al2, wt4h, wt4l, b4, inv2, b256b, b256a, N, 256, 512);
    k_scatter<256><<<cdiv(E2, 32), 256>>>(src2, dst2, inv2, b256b, b256a, E2);
    k_relu<<<cdiv(N * 64, 256), 256>>>(b256a, out_zg, N * 64);
}

// round 7
// speedup vs baseline: 2.3113x; 1.2038x over previous
#include <cuda_runtime.h>
#include <cuda_bf16.h>
#include <math.h>
#include <stdint.h>

// ---------------------------------------------------------------------------
// GCN encoder stack — HMMA split GEMM + CSR gather-aggregation (no atomics).
//   z   = relu(A1n(relu(A1n(x W1)+b1) W2)+b2)
//   z_g = relu(A2n(relu((A2n z) W3 + b3) W4)+b4)   (layer3: A(zW)=(Az)W)
// ---------------------------------------------------------------------------

#define NMAX 50048
#define EMAX 400064

__device__ float g_b512a[(size_t)NMAX * 512];   // h1; later aliased as b256c
__device__ float g_b512b[(size_t)NMAX * 512];   // init1/agg1
__device__ float g_b256a[(size_t)NMAX * 256];
__device__ float g_b256b[(size_t)NMAX * 256];
__device__ int   g_deg1[NMAX];
__device__ int   g_deg2[NMAX];
__device__ float g_inv1[NMAX];
__device__ float g_inv2[NMAX];
// CSR
__device__ int   g_rs1[NMAX + 1];
__device__ int   g_rs2[NMAX + 1];
__device__ int   g_cur1[NMAX];
__device__ int   g_cur2[NMAX];
__device__ int   g_sorted1[EMAX];
__device__ int   g_sorted2[EMAX];

// bf16 split buffers for GEMM A operands
__device__ __nv_bfloat16 g_ah[(size_t)NMAX * 512];
__device__ __nv_bfloat16 g_al[(size_t)NMAX * 512];
__device__ __nv_bfloat16 g_ah2[(size_t)NMAX * 512];
__device__ __nv_bfloat16 g_al2[(size_t)NMAX * 512];
// pre-transposed weights, K-major [N_out, K], bf16 hi/lo
__device__ __nv_bfloat16 g_wt1h[512 * 512], g_wt1l[512 * 512];
__device__ __nv_bfloat16 g_wt2h[256 * 512], g_wt2l[256 * 512];
__device__ __nv_bfloat16 g_wt3h[512 * 256], g_wt3l[512 * 256];
__device__ __nv_bfloat16 g_wt4h[256 * 512], g_wt4l[256 * 512];

// ---------------------------------------------------------------------------
// PTX helpers
// ---------------------------------------------------------------------------
__device__ __forceinline__ uint32_t smem_u32(const void* p) {
    uint32_t a;
    asm("{ .reg .u64 t; cvta.to.shared.u64 t, %1; cvt.u32.u64 %0, t; }" : "=r"(a) : "l"(p));
    return a;
}

__device__ __forceinline__ void cp_async16(uint32_t dst, const void* src, bool pred) {
    int sz = pred ? 16 : 0;
    asm volatile("cp.async.cg.shared.global [%0], [%1], 16, %2;"
                 :: "r"(dst), "l"(src), "r"(sz) : "memory");
}
#define CP_COMMIT() asm volatile("cp.async.commit_group;" ::: "memory")
#define CP_WAIT(n)  asm volatile("cp.async.wait_group %0;" :: "n"(n) : "memory")

#define LDMATRIX_X4(r0, r1, r2, r3, addr) \
    asm volatile("ldmatrix.sync.aligned.m8n8.x4.shared.b16 {%0,%1,%2,%3}, [%4];" \
                 : "=r"(r0), "=r"(r1), "=r"(r2), "=r"(r3) : "r"(addr))

__device__ __forceinline__ void mma_bf16(float* c, const uint32_t* a, const uint32_t* b) {
    asm volatile(
        "mma.sync.aligned.m16n8k16.row.col.f32.bf16.bf16.f32 "
        "{%0,%1,%2,%3}, {%4,%5,%6,%7}, {%8,%9}, {%0,%1,%2,%3};"
        : "+f"(c[0]), "+f"(c[1]), "+f"(c[2]), "+f"(c[3])
        : "r"(a[0]), "r"(a[1]), "r"(a[2]), "r"(a[3]), "r"(b[0]), "r"(b[1]));
}

// ---------------------------------------------------------------------------
// degree / normalization / CSR build
// ---------------------------------------------------------------------------
__global__ void k_zero_deg(int* d1, int* d2, int n) {
    int i = blockIdx.x * blockDim.x + threadIdx.x;
    if (i < n) { d1[i] = 0; d2[i] = 0; }
}
__global__ void k_deg(const int* __restrict__ dst, int E, int* deg) {
    int i = blockIdx.x * blockDim.x + threadIdx.x;
    if (i < E) atomicAdd(&deg[dst[i]], 1);
}
__global__ void k_inv(const int* __restrict__ d1, const int* __restrict__ d2,
                      float* i1, float* i2, int n) {
    int i = blockIdx.x * blockDim.x + threadIdx.x;
    if (i < n) {
        i1[i] = rsqrtf((float)d1[i] + 1.0f);
        i2[i] = rsqrtf((float)d2[i] + 1.0f);
    }
}

// single-block-per-graph prefix sum: rs[i+1]=cumsum(deg), cur[i]=rs[i]
__global__ __launch_bounds__(1024)
void k_scan2(const int* __restrict__ deg1, const int* __restrict__ deg2,
             int* rs1, int* cur1, int* rs2, int* cur2, int n) {
    const int* deg = blockIdx.x ? deg2 : deg1;
    int* rs  = blockIdx.x ? rs2  : rs1;
    int* cur = blockIdx.x ? cur2 : cur1;
    __shared__ int sm[1024];
    __shared__ int carry;
    int tid = threadIdx.x;
    if (tid == 0) { carry = 0; rs[0] = 0; }
    __syncthreads();
    for (int base = 0; base < n; base += 1024) {
        int i = base + tid;
        int v = (i < n) ? deg[i] : 0;
        sm[tid] = v;
        __syncthreads();
#pragma unroll
        for (int off = 1; off < 1024; off <<= 1) {
            int t = (tid >= off) ? sm[tid - off] : 0;
            __syncthreads();
            sm[tid] += t;
            __syncthreads();
        }
        int inc = sm[tid] + carry;
        if (i < n) { rs[i + 1] = inc; cur[i] = inc - v; }
        __syncthreads();
        if (tid == 1023) carry = inc;
        __syncthreads();
    }
}

__global__ void k_bin(const int* __restrict__ src, const int* __restrict__ dst,
                      int E, int* cursor, int* __restrict__ sorted) {
    int i = blockIdx.x * blockDim.x + threadIdx.x;
    if (i < E) {
        int p = atomicAdd(&cursor[dst[i]], 1);
        sorted[p] = src[i];
    }
}

// ---------------------------------------------------------------------------
// fp32 -> bf16 hi/lo split (input x only)
// ---------------------------------------------------------------------------
__global__ void k_cvt(const float* __restrict__ in, __nv_bfloat16* __restrict__ hi,
                      __nv_bfloat16* __restrict__ lo, int n4) {
    int i = blockIdx.x * blockDim.x + threadIdx.x;
    if (i >= n4) return;
    float4 v = ((const float4*)in)[i];
    __nv_bfloat16 hx = __float2bfloat16_rn(v.x), hy = __float2bfloat16_rn(v.y);
    __nv_bfloat16 hz = __float2bfloat16_rn(v.z), hw = __float2bfloat16_rn(v.w);
    __nv_bfloat16 lx = __float2bfloat16_rn(v.x - __bfloat162float(hx));
    __nv_bfloat16 ly = __float2bfloat16_rn(v.y - __bfloat162float(hy));
    __nv_bfloat16 lz = __float2bfloat16_rn(v.z - __bfloat162float(hz));
    __nv_bfloat16 lw = __float2bfloat16_rn(v.w - __bfloat162float(hw));
    __nv_bfloat162* H = (__nv_bfloat162*)hi;
    __nv_bfloat162* L = (__nv_bfloat162*)lo;
    H[2 * i]     = __nv_bfloat162(hx, hy);
    H[2 * i + 1] = __nv_bfloat162(hz, hw);
    L[2 * i]     = __nv_bfloat162(lx, ly);
    L[2 * i + 1] = __nv_bfloat162(lz, lw);
}

// weight transpose + split: W[K,N] -> Wt_hi/lo[N,K]
__global__ void k_wt(const float* __restrict__ W, __nv_bfloat16* __restrict__ th,
                     __nv_bfloat16* __restrict__ tl, int K, int N) {
    int idx = blockIdx.x * blockDim.x + threadIdx.x;
    if (idx >= N * K) return;
    int n = idx / K, k = idx - n * K;
    float w = W[(size_t)k * N + n];
    __nv_bfloat16 h = __float2bfloat16_rn(w);
    th[idx] = h;
    tl[idx] = __float2bfloat16_rn(w - __bfloat162float(h));
}

// ---------------------------------------------------------------------------
// CSR aggregation: one warp per dst row.
//   acc = init[row] + sum_e inv[src]*inv[row] * h[src]
// EPI: 0 = relu -> outA(f32)
//      1 = relu -> bf16 split outA/outB
//      2 = relu -> outA(f32), relu*inv2^2 -> outB(f32)
//      3 = bf16 split outA/outB (no relu)
// ---------------------------------------------------------------------------
template<int D, int EPI>
__global__ __launch_bounds__(256)
void k_agg(const int* __restrict__ row_start, const int* __restrict__ sorted_src,
           const float* __restrict__ inv, const float* __restrict__ inv2,
           const float* __restrict__ h, const float* __restrict__ init,
           void* __restrict__ outAv, void* __restrict__ outBv, int n) {
    constexpr int Q = D / 128;             // float4 per lane
    int warp = (blockIdx.x * 256 + threadIdx.x) >> 5;
    int lane = threadIdx.x & 31;
    if (warp >= n) return;

    float4 acc[Q];
    const float4* ip = (const float4*)(init + (size_t)warp * D);
#pragma unroll
    for (int q = 0; q < Q; q++) acc[q] = ip[lane + 32 * q];

    const int s0 = row_start[warp];
    const int s1 = row_start[warp + 1];
    const float invd = __ldg(inv + warp);

    int e = s0;
    int s = (e < s1) ? __ldg(sorted_src + e) : 0;
    while (e < s1) {
        int sn = (e + 1 < s1) ? __ldg(sorted_src + e + 1) : 0;
        float c = __ldg(inv + s) * invd;
        const float4* hp = (const float4*)(h + (size_t)s * D);
#pragma unroll
        for (int q = 0; q < Q; q++) {
            float4 v = hp[lane + 32 * q];
            acc[q].x = fmaf(v.x, c, acc[q].x);
            acc[q].y = fmaf(v.y, c, acc[q].y);
            acc[q].z = fmaf(v.z, c, acc[q].z);
            acc[q].w = fmaf(v.w, c, acc[q].w);
        }
        s = sn;
        ++e;
    }

    if (EPI == 0) {
        float* oa = (float*)outAv;
#pragma unroll
        for (int q = 0; q < Q; q++) {
            float4 v = acc[q];
            v.x = fmaxf(v.x, 0.f); v.y = fmaxf(v.y, 0.f);
            v.z = fmaxf(v.z, 0.f); v.w = fmaxf(v.w, 0.f);
            ((float4*)(oa + (size_t)warp * D))[lane + 32 * q] = v;
        }
    } else if (EPI == 2) {
        float* oa = (float*)outAv;
        float* ob = (float*)outBv;
        float sc = __ldg(inv2 + warp); sc *= sc;
#pragma unroll
        for (int q = 0; q < Q; q++) {
            float4 v = acc[q];
            v.x = fmaxf(v.x, 0.f); v.y = fmaxf(v.y, 0.f);
            v.z = fmaxf(v.z, 0.f); v.w = fmaxf(v.w, 0.f);
            ((float4*)(oa + (size_t)warp * D))[lane + 32 * q] = v;
            ((float4*)(ob + (size_t)warp * D))[lane + 32 * q] =
                make_float4(v.x * sc, v.y * sc, v.z * sc, v.w * sc);
        }
    } else {  // EPI 1 / 3: bf16 hi/lo split (EPI 1 applies relu first)
        __nv_bfloat16* CH = (__nv_bfloat16*)outAv;
        __nv_bfloat16* CL = (__nv_bfloat16*)outBv;
#pragma unroll
        for (int q = 0; q < Q; q++) {
            float4 v = acc[q];
            if (EPI == 1) {
                v.x = fmaxf(v.x, 0.f); v.y = fmaxf(v.y, 0.f);
                v.z = fmaxf(v.z, 0.f); v.w = fmaxf(v.w, 0.f);
            }
            __nv_bfloat16 hx = __float2bfloat16_rn(v.x), hy = __float2bfloat16_rn(v.y);
            __nv_bfloat16 hz = __float2bfloat16_rn(v.z), hw = __float2bfloat16_rn(v.w);
            __nv_bfloat16 lx = __float2bfloat16_rn(v.x - __bfloat162float(hx));
            __nv_bfloat16 ly = __float2bfloat16_rn(v.y - __bfloat162float(hy));
            __nv_bfloat16 lz = __float2bfloat16_rn(v.z - __bfloat162float(hz));
            __nv_bfloat16 lw = __float2bfloat16_rn(v.w - __bfloat162float(hw));
            size_t base = (size_t)warp * D + 4 * (lane + 32 * q);
            ((__nv_bfloat162*)(CH + base))[0] = __nv_bfloat162(hx, hy);
            ((__nv_bfloat162*)(CH + base))[1] = __nv_bfloat162(hz, hw);
            ((__nv_bfloat162*)(CL + base))[0] = __nv_bfloat162(lx, ly);
            ((__nv_bfloat162*)(CL + base))[1] = __nv_bfloat162(lz, lw);
        }
    }
}

// ---------------------------------------------------------------------------
// HMMA GEMM: acc[M,N] = A[M,K] * Wt[N,K]^T, fused epilogue:
//   MODE 0: C0 = acc ; C1 = acc*inv[row]^2 + bias[col]
//   MODE 1: v = relu(acc + bias[col]); C0 = bf16_hi(v), C1 = bf16_lo(v)
// ---------------------------------------------------------------------------
#define STAGE_BYTES 65536
#define GEMM_SMEM_BYTES (2 * STAGE_BYTES)

template<int MODE>
__global__ __launch_bounds__(512)
void k_mmagemm(const __nv_bfloat16* __restrict__ Ah, const __nv_bfloat16* __restrict__ Al,
               const __nv_bfloat16* __restrict__ Bh, const __nv_bfloat16* __restrict__ Bl,
               const float* __restrict__ bias, const float* __restrict__ inv,
               void* __restrict__ C0v, void* __restrict__ C1v,
               int M, int N, int K) {
    extern __shared__ uint8_t smem[];
    const uint32_t sb = smem_u32(smem);

    const int tid  = threadIdx.x;
    const int wid  = tid >> 5;
    const int lane = tid & 31;
    const int wr   = wid >> 2;
    const int wc   = wid & 3;
    const int m0   = blockIdx.y * 128;
    const int n0   = blockIdx.x * 128;

    const int lrow = tid >> 3;
    const int lc16 = tid & 7;

    const int a_r = (lane & 7) + ((lane >> 3) & 1) * 8;
    const int a_h = (lane >> 4) & 1;
    const int b_r = (lane & 7) + ((lane >> 4) & 1) * 8;
    const int b_h = (lane >> 3) & 1;

    float acc[2][4][4];
#pragma unroll
    for (int i = 0; i < 2; i++)
#pragma unroll
        for (int j = 0; j < 4; j++)
#pragma unroll
            for (int q = 0; q < 4; q++) acc[i][j][q] = 0.f;

    const int kIters = K >> 6;

    auto load_chunk = [&](int stage, int k0) {
        const uint32_t sbase = sb + stage * STAGE_BYTES;
#pragma unroll
        for (int j = 0; j < 2; j++) {
            const int row = lrow + j * 64;
            const int c16 = lc16;
            const uint32_t soff = (uint32_t)(row * 128 + ((c16 ^ (row & 7)) << 4));
            const bool aok = (m0 + row) < M;
            const int arow = aok ? (m0 + row) : (M - 1);
            const size_t ga = (size_t)arow * K + k0 + c16 * 8;
            cp_async16(sbase + soff,         Ah + ga, aok);
            cp_async16(sbase + 16384 + soff, Al + ga, aok);
            const size_t gb = (size_t)(n0 + row) * K + k0 + c16 * 8;
            cp_async16(sbase + 32768 + soff, Bh + gb, true);
            cp_async16(sbase + 49152 + soff, Bl + gb, true);
        }
        CP_COMMIT();
    };

    load_chunk(0, 0);

    int stage = 0;
    for (int it = 0; it < kIters; it++) {
        if (it + 1 < kIters) load_chunk(stage ^ 1, (it + 1) << 6);
        if (it + 1 < kIters) { CP_WAIT(1); } else { CP_WAIT(0); }
        __syncthreads();

        const uint32_t A_H = sb + stage * STAGE_BYTES;
        const uint32_t A_L = A_H + 16384;
        const uint32_t B_H = A_H + 32768;
        const uint32_t B_L = A_H + 49152;

#pragma unroll
        for (int ks = 0; ks < 4; ks++) {
            uint32_t af_h[2][4], af_l[2][4];
#pragma unroll
            for (int am = 0; am < 2; am++) {
                const int row = wr * 32 + am * 16 + a_r;
                const int c16 = ks * 2 + a_h;
                const uint32_t off = (uint32_t)(row * 128 + ((c16 ^ (row & 7)) << 4));
                LDMATRIX_X4(af_h[am][0], af_h[am][1], af_h[am][2], af_h[am][3], A_H + off);
                LDMATRIX_X4(af_l[am][0], af_l[am][1], af_l[am][2], af_l[am][3], A_L + off);
            }
            uint32_t bf_h[4][2], bf_l[4][2];
#pragma unroll
            for (int bp = 0; bp < 2; bp++) {
                const int row = wc * 32 + bp * 16 + b_r;
                const int c16 = ks * 2 + b_h;
                const uint32_t off = (uint32_t)(row * 128 + ((c16 ^ (row & 7)) << 4));
                uint32_t r0, r1, r2, r3;
                LDMATRIX_X4(r0, r1, r2, r3, B_H + off);
                bf_h[bp * 2][0] = r0; bf_h[bp * 2][1] = r1;
                bf_h[bp * 2 + 1][0] = r2; bf_h[bp * 2 + 1][1] = r3;
                LDMATRIX_X4(r0, r1, r2, r3, B_L + off);
                bf_l[bp * 2][0] = r0; bf_l[bp * 2][1] = r1;
                bf_l[bp * 2 + 1][0] = r2; bf_l[bp * 2 + 1][1] = r3;
            }
#pragma unroll
            for (int am = 0; am < 2; am++)
#pragma unroll
                for (int bn = 0; bn < 4; bn++) {
                    mma_bf16(acc[am][bn], af_h[am], bf_h[bn]);
                    mma_bf16(acc[am][bn], af_h[am], bf_l[bn]);
                    mma_bf16(acc[am][bn], af_l[am], bf_h[bn]);
                }
        }
        __syncthreads();
        stage ^= 1;
    }

    // ---- fused epilogue ----
    const int r_base = m0 + wr * 32 + (lane >> 2);
    const int c_base = n0 + wc * 32 + (lane & 3) * 2;
#pragma unroll
    for (int am = 0; am < 2; am++) {
#pragma unroll
        for (int bn = 0; bn < 4; bn++) {
            const int col = c_base + bn * 8;
            const float bx = __ldg(bias + col), by = __ldg(bias + col + 1);
#pragma unroll
            for (int h = 0; h < 2; h++) {
                const int row = r_base + am * 16 + h * 8;
                if (row < M) {
                    float v0 = acc[am][bn][h * 2];
                    float v1 = acc[am][bn][h * 2 + 1];
                    if (MODE == 0) {
                        float* Ch = (float*)C0v;
                        float* Cg = (float*)C1v;
                        float s = __ldg(inv + row); s *= s;
                        *(float2*)(Ch + (size_t)row * N + col) = make_float2(v0, v1);
                        *(float2*)(Cg + (size_t)row * N + col) =
                            make_float2(v0 * s + bx, v1 * s + by);
                    } else {
                        float u0 = fmaxf(v0 + bx, 0.f);
                        float u1 = fmaxf(v1 + by, 0.f);
                        __nv_bfloat16 h0 = __float2bfloat16_rn(u0);
                        __nv_bfloat16 h1 = __float2bfloat16_rn(u1);
                        __nv_bfloat16 l0 = __float2bfloat16_rn(u0 - __bfloat162float(h0));
                        __nv_bfloat16 l1 = __float2bfloat16_rn(u1 - __bfloat162float(h1));
                        __nv_bfloat16* CH = (__nv_bfloat16*)C0v;
                        __nv_bfloat16* CL = (__nv_bfloat16*)C1v;
                        *(__nv_bfloat162*)(CH + (size_t)row * N + col) = __nv_bfloat162(h0, h1);
                        *(__nv_bfloat162*)(CL + (size_t)row * N + col) = __nv_bfloat162(l0, l1);
                    }
                }
            }
        }
    }
}

// ---------------------------------------------------------------------------
// launch
// ---------------------------------------------------------------------------
static inline int cdiv(int a, int b) { return (a + b - 1) / b; }

extern "C" void kernel_launch(void* const* d_in, const int* in_sizes, int n_in,
                              void* d_out, int out_size) {
    if (n_in < 11) return;
    const float* x  = (const float*)d_in[0];
    const int* ei1  = (const int*)d_in[1];
    const int* ei2  = (const int*)d_in[2];
    const float* W1 = (const float*)d_in[3];
    const float* b1 = (const float*)d_in[4];
    const float* W2 = (const float*)d_in[5];
    const float* b2 = (const float*)d_in[6];
    const float* W3 = (const float*)d_in[7];
    const float* b3 = (const float*)d_in[8];
    const float* W4 = (const float*)d_in[9];
    const float* b4 = (const float*)d_in[10];

    const int N  = in_sizes[0] / 512;
    const int E1 = in_sizes[1] / 2;
    const int E2 = in_sizes[2] / 2;
    const int* src1 = ei1;
    const int* dst1 = ei1 + E1;
    const int* src2 = ei2;
    const int* dst2 = ei2 + E2;

    float *b512a, *b512b, *b256a, *b256b, *inv1, *inv2;
    int *deg1, *deg2, *rs1, *rs2, *cur1, *cur2, *sorted1, *sorted2;
    __nv_bfloat16 *ah, *al, *ah2, *al2;
    __nv_bfloat16 *wt1h, *wt1l, *wt2h, *wt2l, *wt3h, *wt3l, *wt4h, *wt4l;
    cudaGetSymbolAddress((void**)&b512a, g_b512a);
    cudaGetSymbolAddress((void**)&b512b, g_b512b);
    cudaGetSymbolAddress((void**)&b256a, g_b256a);
    cudaGetSymbolAddress((void**)&b256b, g_b256b);
    cudaGetSymbolAddress((void**)&deg1,  g_deg1);
    cudaGetSymbolAddress((void**)&deg2,  g_deg2);
    cudaGetSymbolAddress((void**)&inv1,  g_inv1);
    cudaGetSymbolAddress((void**)&inv2,  g_inv2);
    cudaGetSymbolAddress((void**)&rs1,   g_rs1);
    cudaGetSymbolAddress((void**)&rs2,   g_rs2);
    cudaGetSymbolAddress((void**)&cur1,  g_cur1);
    cudaGetSymbolAddress((void**)&cur2,  g_cur2);
    cudaGetSymbolAddress((void**)&sorted1, g_sorted1);
    cudaGetSymbolAddress((void**)&sorted2, g_sorted2);
    cudaGetSymbolAddress((void**)&ah,    g_ah);
    cudaGetSymbolAddress((void**)&al,    g_al);
    cudaGetSymbolAddress((void**)&ah2,   g_ah2);
    cudaGetSymbolAddress((void**)&al2,   g_al2);
    cudaGetSymbolAddress((void**)&wt1h,  g_wt1h);  cudaGetSymbolAddress((void**)&wt1l, g_wt1l);
    cudaGetSymbolAddress((void**)&wt2h,  g_wt2h);  cudaGetSymbolAddress((void**)&wt2l, g_wt2l);
    cudaGetSymbolAddress((void**)&wt3h,  g_wt3h);  cudaGetSymbolAddress((void**)&wt3l, g_wt3l);
    cudaGetSymbolAddress((void**)&wt4h,  g_wt4h);  cudaGetSymbolAddress((void**)&wt4l, g_wt4l);

    float* b256c = b512a;  // alias: h1 region free after AGG1

    cudaFuncSetAttribute(k_mmagemm<0>,
                         cudaFuncAttributeMaxDynamicSharedMemorySize, GEMM_SMEM_BYTES);
    cudaFuncSetAttribute(k_mmagemm<1>,
                         cudaFuncAttributeMaxDynamicSharedMemorySize, GEMM_SMEM_BYTES);

    float* out_z  = (float*)d_out;
    float* out_zg = out_z + (size_t)N * 256;
    const int rowT = cdiv(N, 128);
    const int aggB = cdiv(N * 32, 256);

    // ---- prep: weights, degrees, normalization, CSR ----
    k_wt<<<cdiv(512 * 512, 256), 256>>>(W1, wt1h, wt1l, 512, 512);
    k_wt<<<cdiv(256 * 512, 256), 256>>>(W2, wt2h, wt2l, 512, 256);
    k_wt<<<cdiv(512 * 256, 256), 256>>>(W3, wt3h, wt3l, 256, 512);
    k_wt<<<cdiv(256 * 512, 256), 256>>>(W4, wt4h, wt4l, 512, 256);
    k_zero_deg<<<cdiv(N, 256), 256>>>(deg1, deg2, N);
    k_deg<<<cdiv(E1, 256), 256>>>(dst1, E1, deg1);
    k_deg<<<cdiv(E2, 256), 256>>>(dst2, E2, deg2);
    k_inv<<<cdiv(N, 256), 256>>>(deg1, deg2, inv1, inv2, N);
    k_scan2<<<2, 1024>>>(deg1, deg2, rs1, cur1, rs2, cur2, N);
    k_bin<<<cdiv(E1, 256), 256>>>(src1, dst1, E1, cur1, sorted1);
    k_bin<<<cdiv(E2, 256), 256>>>(src2, dst2, E2, cur2, sorted2);

    // ---- Layer 1: GEMM1 (h->b512a, init->b512b); AGG1 epi relu+split -> ah/al ----
    k_cvt<<<cdiv(N * 128, 256), 256>>>(x, ah, al, N * 128);
    k_mmagemm<0><<<dim3(4, rowT), 512, GEMM_SMEM_BYTES>>>(
        ah, al, wt1h, wt1l, b1, inv1, b512a, b512b, N, 512, 512);
    k_agg<512, 1><<<aggB, 256>>>(rs1, sorted1, inv1, nullptr, b512a, b512b, ah, al, N);

    // ---- Layer 2: GEMM2 (h->b256a, init->b256b); AGG2 epi relu->out_z, *inv2^2->b256c ----
    k_mmagemm<0><<<dim3(2, rowT), 512, GEMM_SMEM_BYTES>>>(
        ah, al, wt2h, wt2l, b2, inv1, b256a, b256b, N, 256, 512);
    k_agg<256, 2><<<aggB, 256>>>(rs1, sorted1, inv1, inv2, b256a, b256b, out_z, b256c, N);

    // ---- Layer 3 (aggregate-first): AGG3 epi split -> ah/al; GEMM3 epi relu+split -> ah2/al2 ----
    k_agg<256, 3><<<aggB, 256>>>(rs2, sorted2, inv2, nullptr, out_z, b256c, ah, al, N);
    k_mmagemm<1><<<dim3(4, rowT), 512, GEMM_SMEM_BYTES>>>(
        ah, al, wt3h, wt3l, b3, inv2, ah2, al2, N, 512, 256);

    // ---- Layer 4: GEMM4 (h->b256a, init->b256b); AGG4 epi relu -> out_zg ----
    k_mmagemm<0><<<dim3(2, rowT), 512, GEMM_SMEM_BYTES>>>(
        ah2, al2, wt4h, wt4l, b4, inv2, b256a, b256b, N, 256, 512);
    k_agg<256, 0><<<aggB, 256>>>(rs2, sorted2, inv2, nullptr, b256a, b256b, out_zg, nullptr, N);
}

// round 9
// speedup vs baseline: 2.3408x; 1.0128x over previous
#include <cuda_runtime.h>
#include <cuda_bf16.h>
#include <math.h>
#include <stdint.h>

// ---------------------------------------------------------------------------
// GCN encoder stack — HMMA split GEMM + CSR gather-aggregation (no atomics),
// edge-batched (MLP x4) with precomputed per-edge coefficients.
//   z   = relu(A1n(relu(A1n(x W1)+b1) W2)+b2)
//   z_g = relu(A2n(relu((A2n z) W3 + b3) W4)+b4)   (layer3: A(zW)=(Az)W)
// ---------------------------------------------------------------------------

#define NMAX 50048
#define EMAX 400064

__device__ float g_b512a[(size_t)NMAX * 512];   // h1; later aliased as b256c
__device__ float g_b512b[(size_t)NMAX * 512];   // init1/agg1
__device__ float g_b256a[(size_t)NMAX * 256];
__device__ float g_b256b[(size_t)NMAX * 256];
__device__ int   g_deg1[NMAX];
__device__ int   g_deg2[NMAX];
__device__ float g_inv1[NMAX];
__device__ float g_inv2[NMAX];
// CSR
__device__ int   g_rs1[NMAX + 1];
__device__ int   g_rs2[NMAX + 1];
__device__ int   g_cur1[NMAX];
__device__ int   g_cur2[NMAX];
__device__ int2  g_edges1[EMAX];   // .x = src, .y = bitcast(inv[src])
__device__ int2  g_edges2[EMAX];

// bf16 split buffers for GEMM A operands
__device__ __nv_bfloat16 g_ah[(size_t)NMAX * 512];
__device__ __nv_bfloat16 g_al[(size_t)NMAX * 512];
__device__ __nv_bfloat16 g_ah2[(size_t)NMAX * 512];
__device__ __nv_bfloat16 g_al2[(size_t)NMAX * 512];
// pre-transposed weights, K-major [N_out, K], bf16 hi/lo
__device__ __nv_bfloat16 g_wt1h[512 * 512], g_wt1l[512 * 512];
__device__ __nv_bfloat16 g_wt2h[256 * 512], g_wt2l[256 * 512];
__device__ __nv_bfloat16 g_wt3h[512 * 256], g_wt3l[512 * 256];
__device__ __nv_bfloat16 g_wt4h[256 * 512], g_wt4l[256 * 512];

// ---------------------------------------------------------------------------
// PTX helpers
// ---------------------------------------------------------------------------
__device__ __forceinline__ uint32_t smem_u32(const void* p) {
    uint32_t a;
    asm("{ .reg .u64 t; cvta.to.shared.u64 t, %1; cvt.u32.u64 %0, t; }" : "=r"(a) : "l"(p));
    return a;
}

__device__ __forceinline__ void cp_async16(uint32_t dst, const void* src, bool pred) {
    int sz = pred ? 16 : 0;
    asm volatile("cp.async.cg.shared.global [%0], [%1], 16, %2;"
                 :: "r"(dst), "l"(src), "r"(sz) : "memory");
}
#define CP_COMMIT() asm volatile("cp.async.commit_group;" ::: "memory")
#define CP_WAIT(n)  asm volatile("cp.async.wait_group %0;" :: "n"(n) : "memory")

#define LDMATRIX_X4(r0, r1, r2, r3, addr) \
    asm volatile("ldmatrix.sync.aligned.m8n8.x4.shared.b16 {%0,%1,%2,%3}, [%4];" \
                 : "=r"(r0), "=r"(r1), "=r"(r2), "=r"(r3) : "r"(addr))

__device__ __forceinline__ void mma_bf16(float* c, const uint32_t* a, const uint32_t* b) {
    asm volatile(
        "mma.sync.aligned.m16n8k16.row.col.f32.bf16.bf16.f32 "
        "{%0,%1,%2,%3}, {%4,%5,%6,%7}, {%8,%9}, {%0,%1,%2,%3};"
        : "+f"(c[0]), "+f"(c[1]), "+f"(c[2]), "+f"(c[3])
        : "r"(a[0]), "r"(a[1]), "r"(a[2]), "r"(a[3]), "r"(b[0]), "r"(b[1]));
}

// ---------------------------------------------------------------------------
// degree / normalization / CSR build
// ---------------------------------------------------------------------------
__global__ void k_zero_deg(int* d1, int* d2, int n) {
    int i = blockIdx.x * blockDim.x + threadIdx.x;
    if (i < n) { d1[i] = 0; d2[i] = 0; }
}
__global__ void k_deg(const int* __restrict__ dst, int E, int* deg) {
    int i = blockIdx.x * blockDim.x + threadIdx.x;
    if (i < E) atomicAdd(&deg[dst[i]], 1);
}
__global__ void k_inv(const int* __restrict__ d1, const int* __restrict__ d2,
                      float* i1, float* i2, int n) {
    int i = blockIdx.x * blockDim.x + threadIdx.x;
    if (i < n) {
        i1[i] = rsqrtf((float)d1[i] + 1.0f);
        i2[i] = rsqrtf((float)d2[i] + 1.0f);
    }
}

// single-block-per-graph prefix sum: rs[i+1]=cumsum(deg), cur[i]=rs[i]
__global__ __launch_bounds__(1024)
void k_scan2(const int* __restrict__ deg1, const int* __restrict__ deg2,
             int* rs1, int* cur1, int* rs2, int* cur2, int n) {
    const int* deg = blockIdx.x ? deg2 : deg1;
    int* rs  = blockIdx.x ? rs2  : rs1;
    int* cur = blockIdx.x ? cur2 : cur1;
    __shared__ int sm[1024];
    __shared__ int carry;
    int tid = threadIdx.x;
    if (tid == 0) { carry = 0; rs[0] = 0; }
    __syncthreads();
    for (int base = 0; base < n; base += 1024) {
        int i = base + tid;
        int v = (i < n) ? deg[i] : 0;
        sm[tid] = v;
        __syncthreads();
#pragma unroll
        for (int off = 1; off < 1024; off <<= 1) {
            int t = (tid >= off) ? sm[tid - off] : 0;
            __syncthreads();
            sm[tid] += t;
            __syncthreads();
        }
        int inc = sm[tid] + carry;
        if (i < n) { rs[i + 1] = inc; cur[i] = inc - v; }
        __syncthreads();
        if (tid == 1023) carry = inc;
        __syncthreads();
    }
}

// bin edges by dst; store (src, inv[src]) so the agg loop has no dependent load
__global__ void k_bin(const int* __restrict__ src, const int* __restrict__ dst,
                      const float* __restrict__ inv, int E, int* cursor,
                      int2* __restrict__ edges) {
    int i = blockIdx.x * blockDim.x + threadIdx.x;
    if (i < E) {
        int s = src[i];
        int p = atomicAdd(&cursor[dst[i]], 1);
        edges[p] = make_int2(s, __float_as_int(__ldg(inv + s)));
    }
}

// ---------------------------------------------------------------------------
// fp32 -> bf16 hi/lo split (input x only)
// ---------------------------------------------------------------------------
__global__ void k_cvt(const float* __restrict__ in, __nv_bfloat16* __restrict__ hi,
                      __nv_bfloat16* __restrict__ lo, int n4) {
    int i = blockIdx.x * blockDim.x + threadIdx.x;
    if (i >= n4) return;
    float4 v = ((const float4*)in)[i];
    __nv_bfloat16 hx = __float2bfloat16_rn(v.x), hy = __float2bfloat16_rn(v.y);
    __nv_bfloat16 hz = __float2bfloat16_rn(v.z), hw = __float2bfloat16_rn(v.w);
    __nv_bfloat16 lx = __float2bfloat16_rn(v.x - __bfloat162float(hx));
    __nv_bfloat16 ly = __float2bfloat16_rn(v.y - __bfloat162float(hy));
    __nv_bfloat16 lz = __float2bfloat16_rn(v.z - __bfloat162float(hz));
    __nv_bfloat16 lw = __float2bfloat16_rn(v.w - __bfloat162float(hw));
    __nv_bfloat162* H = (__nv_bfloat162*)hi;
    __nv_bfloat162* L = (__nv_bfloat162*)lo;
    H[2 * i]     = __nv_bfloat162(hx, hy);
    H[2 * i + 1] = __nv_bfloat162(hz, hw);
    L[2 * i]     = __nv_bfloat162(lx, ly);
    L[2 * i + 1] = __nv_bfloat162(lz, lw);
}

// weight transpose + split: W[K,N] -> Wt_hi/lo[N,K]
__global__ void k_wt(const float* __restrict__ W, __nv_bfloat16* __restrict__ th,
                     __nv_bfloat16* __restrict__ tl, int K, int N) {
    int idx = blockIdx.x * blockDim.x + threadIdx.x;
    if (idx >= N * K) return;
    int n = idx / K, k = idx - n * K;
    float w = W[(size_t)k * N + n];
    __nv_bfloat16 h = __float2bfloat16_rn(w);
    th[idx] = h;
    tl[idx] = __float2bfloat16_rn(w - __bfloat162float(h));
}

// ---------------------------------------------------------------------------
// CSR aggregation: one warp per dst row, edges batched x4 for MLP.
//   acc = init[row] + sum_e coef_e * h[src_e]
// EPI: 0 = relu -> outA(f32)
//      1 = relu -> bf16 split outA/outB
//      2 = relu -> outA(f32), relu*inv2^2 -> outB(f32)
//      3 = bf16 split outA/outB (no relu)
// ---------------------------------------------------------------------------
template<int D, int EPI>
__global__ __launch_bounds__(256)
void k_agg(const int* __restrict__ row_start, const int2* __restrict__ edges,
           const float* __restrict__ inv, const float* __restrict__ inv2,
           const float* __restrict__ h, const float* __restrict__ init,
           void* __restrict__ outAv, void* __restrict__ outBv, int n) {
    constexpr int Q = D / 128;             // float4 per lane
    int warp = (blockIdx.x * 256 + threadIdx.x) >> 5;
    int lane = threadIdx.x & 31;
    if (warp >= n) return;

    float4 acc[Q];
    const float4* ip = (const float4*)(init + (size_t)warp * D);
#pragma unroll
    for (int q = 0; q < Q; q++) acc[q] = ip[lane + 32 * q];

    const int s0 = row_start[warp];
    const int s1 = row_start[warp + 1];
    const float invd = __ldg(inv + warp);

    int e = s0;
    // batched x4: front-load 4 rows' gathers (MLP = 4*Q)
    for (; e + 4 <= s1; e += 4) {
        int2 e0 = __ldg(edges + e);
        int2 e1 = __ldg(edges + e + 1);
        int2 e2 = __ldg(edges + e + 2);
        int2 e3 = __ldg(edges + e + 3);
        float c0 = __int_as_float(e0.y) * invd;
        float c1 = __int_as_float(e1.y) * invd;
        float c2 = __int_as_float(e2.y) * invd;
        float c3 = __int_as_float(e3.y) * invd;
        const float4* p0 = (const float4*)(h + (size_t)e0.x * D);
        const float4* p1 = (const float4*)(h + (size_t)e1.x * D);
        const float4* p2 = (const float4*)(h + (size_t)e2.x * D);
        const float4* p3 = (const float4*)(h + (size_t)e3.x * D);
        float4 v0[Q], v1[Q], v2[Q], v3[Q];
#pragma unroll
        for (int q = 0; q < Q; q++) v0[q] = p0[lane + 32 * q];
#pragma unroll
        for (int q = 0; q < Q; q++) v1[q] = p1[lane + 32 * q];
#pragma unroll
        for (int q = 0; q < Q; q++) v2[q] = p2[lane + 32 * q];
#pragma unroll
        for (int q = 0; q < Q; q++) v3[q] = p3[lane + 32 * q];
#pragma unroll
        for (int q = 0; q < Q; q++) {
            acc[q].x = fmaf(v0[q].x, c0, acc[q].x);
            acc[q].y = fmaf(v0[q].y, c0, acc[q].y);
            acc[q].z = fmaf(v0[q].z, c0, acc[q].z);
            acc[q].w = fmaf(v0[q].w, c0, acc[q].w);
            acc[q].x = fmaf(v1[q].x, c1, acc[q].x);
            acc[q].y = fmaf(v1[q].y, c1, acc[q].y);
            acc[q].z = fmaf(v1[q].z, c1, acc[q].z);
            acc[q].w = fmaf(v1[q].w, c1, acc[q].w);
            acc[q].x = fmaf(v2[q].x, c2, acc[q].x);
            acc[q].y = fmaf(v2[q].y, c2, acc[q].y);
            acc[q].z = fmaf(v2[q].z, c2, acc[q].z);
            acc[q].w = fmaf(v2[q].w, c2, acc[q].w);
            acc[q].x = fmaf(v3[q].x, c3, acc[q].x);
            acc[q].y = fmaf(v3[q].y, c3, acc[q].y);
            acc[q].z = fmaf(v3[q].z, c3, acc[q].z);
            acc[q].w = fmaf(v3[q].w, c3, acc[q].w);
        }
    }
    // tail
    for (; e < s1; e++) {
        int2 ee = __ldg(edges + e);
        float c = __int_as_float(ee.y) * invd;
        const float4* hp = (const float4*)(h + (size_t)ee.x * D);
#pragma unroll
        for (int q = 0; q < Q; q++) {
            float4 v = hp[lane + 32 * q];
            acc[q].x = fmaf(v.x, c, acc[q].x);
            acc[q].y = fmaf(v.y, c, acc[q].y);
            acc[q].z = fmaf(v.z, c, acc[q].z);
            acc[q].w = fmaf(v.w, c, acc[q].w);
        }
    }

    if (EPI == 0) {
        float* oa = (float*)outAv;
#pragma unroll
        for (int q = 0; q < Q; q++) {
            float4 v = acc[q];
            v.x = fmaxf(v.x, 0.f); v.y = fmaxf(v.y, 0.f);
            v.z = fmaxf(v.z, 0.f); v.w = fmaxf(v.w, 0.f);
            ((float4*)(oa + (size_t)warp * D))[lane + 32 * q] = v;
        }
    } else if (EPI == 2) {
        float* oa = (float*)outAv;
        float* ob = (float*)outBv;
        float sc = __ldg(inv2 + warp); sc *= sc;
#pragma unroll
        for (int q = 0; q < Q; q++) {
            float4 v = acc[q];
            v.x = fmaxf(v.x, 0.f); v.y = fmaxf(v.y, 0.f);
            v.z = fmaxf(v.z, 0.f); v.w = fmaxf(v.w, 0.f);
            ((float4*)(oa + (size_t)warp * D))[lane + 32 * q] = v;
            ((float4*)(ob + (size_t)warp * D))[lane + 32 * q] =
                make_float4(v.x * sc, v.y * sc, v.z * sc, v.w * sc);
        }
    } else {  // EPI 1 / 3: bf16 hi/lo split (EPI 1 applies relu first)
        __nv_bfloat16* CH = (__nv_bfloat16*)outAv;
        __nv_bfloat16* CL = (__nv_bfloat16*)outBv;
#pragma unroll
        for (int q = 0; q < Q; q++) {
            float4 v = acc[q];
            if (EPI == 1) {
                v.x = fmaxf(v.x, 0.f); v.y = fmaxf(v.y, 0.f);
                v.z = fmaxf(v.z, 0.f); v.w = fmaxf(v.w, 0.f);
            }
            __nv_bfloat16 hx = __float2bfloat16_rn(v.x), hy = __float2bfloat16_rn(v.y);
            __nv_bfloat16 hz = __float2bfloat16_rn(v.z), hw = __float2bfloat16_rn(v.w);
            __nv_bfloat16 lx = __float2bfloat16_rn(v.x - __bfloat162float(hx));
            __nv_bfloat16 ly = __float2bfloat16_rn(v.y - __bfloat162float(hy));
            __nv_bfloat16 lz = __float2bfloat16_rn(v.z - __bfloat162float(hz));
            __nv_bfloat16 lw = __float2bfloat16_rn(v.w - __bfloat162float(hw));
            size_t base = (size_t)warp * D + 4 * (lane + 32 * q);
            ((__nv_bfloat162*)(CH + base))[0] = __nv_bfloat162(hx, hy);
            ((__nv_bfloat162*)(CH + base))[1] = __nv_bfloat162(hz, hw);
            ((__nv_bfloat162*)(CL + base))[0] = __nv_bfloat162(lx, ly);
            ((__nv_bfloat162*)(CL + base))[1] = __nv_bfloat162(lz, lw);
        }
    }
}

// ---------------------------------------------------------------------------
// HMMA GEMM: acc[M,N] = A[M,K] * Wt[N,K]^T, fused epilogue:
//   MODE 0: C0 = acc ; C1 = acc*inv[row]^2 + bias[col]
//   MODE 1: v = relu(acc + bias[col]); C0 = bf16_hi(v), C1 = bf16_lo(v)
// ---------------------------------------------------------------------------
#define STAGE_BYTES 65536
#define GEMM_SMEM_BYTES (2 * STAGE_BYTES)

template<int MODE>
__global__ __launch_bounds__(512)
void k_mmagemm(const __nv_bfloat16* __restrict__ Ah, const __nv_bfloat16* __restrict__ Al,
               const __nv_bfloat16* __restrict__ Bh, const __nv_bfloat16* __restrict__ Bl,
               const float* __restrict__ bias, const float* __restrict__ inv,
               void* __restrict__ C0v, void* __restrict__ C1v,
               int M, int N, int K) {
    extern __shared__ uint8_t smem[];
    const uint32_t sb = smem_u32(smem);

    const int tid  = threadIdx.x;
    const int wid  = tid >> 5;
    const int lane = tid & 31;
    const int wr   = wid >> 2;
    const int wc   = wid & 3;
    const int m0   = blockIdx.y * 128;
    const int n0   = blockIdx.x * 128;

    const int lrow = tid >> 3;
    const int lc16 = tid & 7;

    const int a_r = (lane & 7) + ((lane >> 3) & 1) * 8;
    const int a_h = (lane >> 4) & 1;
    const int b_r = (lane & 7) + ((lane >> 4) & 1) * 8;
    const int b_h = (lane >> 3) & 1;

    float acc[2][4][4];
#pragma unroll
    for (int i = 0; i < 2; i++)
#pragma unroll
        for (int j = 0; j < 4; j++)
#pragma unroll
            for (int q = 0; q < 4; q++) acc[i][j][q] = 0.f;

    const int kIters = K >> 6;

    auto load_chunk = [&](int stage, int k0) {
        const uint32_t sbase = sb + stage * STAGE_BYTES;
#pragma unroll
        for (int j = 0; j < 2; j++) {
            const int row = lrow + j * 64;
            const int c16 = lc16;
            const uint32_t soff = (uint32_t)(row * 128 + ((c16 ^ (row & 7)) << 4));
            const bool aok = (m0 + row) < M;
            const int arow = aok ? (m0 + row) : (M - 1);
            const size_t ga = (size_t)arow * K + k0 + c16 * 8;
            cp_async16(sbase + soff,         Ah + ga, aok);
            cp_async16(sbase + 16384 + soff, Al + ga, aok);
            const size_t gb = (size_t)(n0 + row) * K + k0 + c16 * 8;
            cp_async16(sbase + 32768 + soff, Bh + gb, true);
            cp_async16(sbase + 49152 + soff, Bl + gb, true);
        }
        CP_COMMIT();
    };

    load_chunk(0, 0);

    int stage = 0;
    for (int it = 0; it < kIters; it++) {
        if (it + 1 < kIters) load_chunk(stage ^ 1, (it + 1) << 6);
        if (it + 1 < kIters) { CP_WAIT(1); } else { CP_WAIT(0); }
        __syncthreads();

        const uint32_t A_H = sb + stage * STAGE_BYTES;
        const uint32_t A_L = A_H + 16384;
        const uint32_t B_H = A_H + 32768;
        const uint32_t B_L = A_H + 49152;

#pragma unroll
        for (int ks = 0; ks < 4; ks++) {
            uint32_t af_h[2][4], af_l[2][4];
#pragma unroll
            for (int am = 0; am < 2; am++) {
                const int row = wr * 32 + am * 16 + a_r;
                const int c16 = ks * 2 + a_h;
                const uint32_t off = (uint32_t)(row * 128 + ((c16 ^ (row & 7)) << 4));
                LDMATRIX_X4(af_h[am][0], af_h[am][1], af_h[am][2], af_h[am][3], A_H + off);
                LDMATRIX_X4(af_l[am][0], af_l[am][1], af_l[am][2], af_l[am][3], A_L + off);
            }
            uint32_t bf_h[4][2], bf_l[4][2];
#pragma unroll
            for (int bp = 0; bp < 2; bp++) {
                const int row = wc * 32 + bp * 16 + b_r;
                const int c16 = ks * 2 + b_h;
                const uint32_t off = (uint32_t)(row * 128 + ((c16 ^ (row & 7)) << 4));
                uint32_t r0, r1, r2, r3;
                LDMATRIX_X4(r0, r1, r2, r3, B_H + off);
                bf_h[bp * 2][0] = r0; bf_h[bp * 2][1] = r1;
                bf_h[bp * 2 + 1][0] = r2; bf_h[bp * 2 + 1][1] = r3;
                LDMATRIX_X4(r0, r1, r2, r3, B_L + off);
                bf_l[bp * 2][0] = r0; bf_l[bp * 2][1] = r1;
                bf_l[bp * 2 + 1][0] = r2; bf_l[bp * 2 + 1][1] = r3;
            }
#pragma unroll
            for (int am = 0; am < 2; am++)
#pragma unroll
                for (int bn = 0; bn < 4; bn++) {
                    mma_bf16(acc[am][bn], af_h[am], bf_h[bn]);
                    mma_bf16(acc[am][bn], af_h[am], bf_l[bn]);
                    mma_bf16(acc[am][bn], af_l[am], bf_h[bn]);
                }
        }
        __syncthreads();
        stage ^= 1;
    }

    // ---- fused epilogue ----
    const int r_base = m0 + wr * 32 + (lane >> 2);
    const int c_base = n0 + wc * 32 + (lane & 3) * 2;
#pragma unroll
    for (int am = 0; am < 2; am++) {
#pragma unroll
        for (int bn = 0; bn < 4; bn++) {
            const int col = c_base + bn * 8;
            const float bx = __ldg(bias + col), by = __ldg(bias + col + 1);
#pragma unroll
            for (int h = 0; h < 2; h++) {
                const int row = r_base + am * 16 + h * 8;
                if (row < M) {
                    float v0 = acc[am][bn][h * 2];
                    float v1 = acc[am][bn][h * 2 + 1];
                    if (MODE == 0) {
                        float* Ch = (float*)C0v;
                        float* Cg = (float*)C1v;
                        float s = __ldg(inv + row); s *= s;
                        *(float2*)(Ch + (size_t)row * N + col) = make_float2(v0, v1);
                        *(float2*)(Cg + (size_t)row * N + col) =
                            make_float2(v0 * s + bx, v1 * s + by);
                    } else {
                        float u0 = fmaxf(v0 + bx, 0.f);
                        float u1 = fmaxf(v1 + by, 0.f);
                        __nv_bfloat16 h0 = __float2bfloat16_rn(u0);
                        __nv_bfloat16 h1 = __float2bfloat16_rn(u1);
                        __nv_bfloat16 l0 = __float2bfloat16_rn(u0 - __bfloat162float(h0));
                        __nv_bfloat16 l1 = __float2bfloat16_rn(u1 - __bfloat162float(h1));
                        __nv_bfloat16* CH = (__nv_bfloat16*)C0v;
                        __nv_bfloat16* CL = (__nv_bfloat16*)C1v;
                        *(__nv_bfloat162*)(CH + (size_t)row * N + col) = __nv_bfloat162(h0, h1);
                        *(__nv_bfloat162*)(CL + (size_t)row * N + col) = __nv_bfloat162(l0, l1);
                    }
                }
            }
        }
    }
}

// ---------------------------------------------------------------------------
// launch
// ---------------------------------------------------------------------------
static inline int cdiv(int a, int b) { return (a + b - 1) / b; }

extern "C" void kernel_launch(void* const* d_in, const int* in_sizes, int n_in,
                              void* d_out, int out_size) {
    if (n_in < 11) return;
    const float* x  = (const float*)d_in[0];
    const int* ei1  = (const int*)d_in[1];
    const int* ei2  = (const int*)d_in[2];
    const float* W1 = (const float*)d_in[3];
    const float* b1 = (const float*)d_in[4];
    const float* W2 = (const float*)d_in[5];
    const float* b2 = (const float*)d_in[6];
    const float* W3 = (const float*)d_in[7];
    const float* b3 = (const float*)d_in[8];
    const float* W4 = (const float*)d_in[9];
    const float* b4 = (const float*)d_in[10];

    const int N  = in_sizes[0] / 512;
    const int E1 = in_sizes[1] / 2;
    const int E2 = in_sizes[2] / 2;
    const int* src1 = ei1;
    const int* dst1 = ei1 + E1;
    const int* src2 = ei2;
    const int* dst2 = ei2 + E2;

    float *b512a, *b512b, *b256a, *b256b, *inv1, *inv2;
    int *deg1, *deg2, *rs1, *rs2, *cur1, *cur2;
    int2 *edges1, *edges2;
    __nv_bfloat16 *ah, *al, *ah2, *al2;
    __nv_bfloat16 *wt1h, *wt1l, *wt2h, *wt2l, *wt3h, *wt3l, *wt4h, *wt4l;
    cudaGetSymbolAddress((void**)&b512a, g_b512a);
    cudaGetSymbolAddress((void**)&b512b, g_b512b);
    cudaGetSymbolAddress((void**)&b256a, g_b256a);
    cudaGetSymbolAddress((void**)&b256b, g_b256b);
    cudaGetSymbolAddress((void**)&deg1,  g_deg1);
    cudaGetSymbolAddress((void**)&deg2,  g_deg2);
    cudaGetSymbolAddress((void**)&inv1,  g_inv1);
    cudaGetSymbolAddress((void**)&inv2,  g_inv2);
    cudaGetSymbolAddress((void**)&rs1,   g_rs1);
    cudaGetSymbolAddress((void**)&rs2,   g_rs2);
    cudaGetSymbolAddress((void**)&cur1,  g_cur1);
    cudaGetSymbolAddress((void**)&cur2,  g_cur2);
    cudaGetSymbolAddress((void**)&edges1, g_edges1);
    cudaGetSymbolAddress((void**)&edges2, g_edges2);
    cudaGetSymbolAddress((void**)&ah,    g_ah);
    cudaGetSymbolAddress((void**)&al,    g_al);
    cudaGetSymbolAddress((void**)&ah2,   g_ah2);
    cudaGetSymbolAddress((void**)&al2,   g_al2);
    cudaGetSymbolAddress((void**)&wt1h,  g_wt1h);  cudaGetSymbolAddress((void**)&wt1l, g_wt1l);
    cudaGetSymbolAddress((void**)&wt2h,  g_wt2h);  cudaGetSymbolAddress((void**)&wt2l, g_wt2l);
    cudaGetSymbolAddress((void**)&wt3h,  g_wt3h);  cudaGetSymbolAddress((void**)&wt3l, g_wt3l);
    cudaGetSymbolAddress((void**)&wt4h,  g_wt4h);  cudaGetSymbolAddress((void**)&wt4l, g_wt4l);

    float* b256c = b512a;  // alias: h1 region free after AGG1

    cudaFuncSetAttribute(k_mmagemm<0>,
                         cudaFuncAttributeMaxDynamicSharedMemorySize, GEMM_SMEM_BYTES);
    cudaFuncSetAttribute(k_mmagemm<1>,
                         cudaFuncAttributeMaxDynamicSharedMemorySize, GEMM_SMEM_BYTES);

    float* out_z  = (float*)d_out;
    float* out_zg = out_z + (size_t)N * 256;
    const int rowT = cdiv(N, 128);
    const int aggB = cdiv(N * 32, 256);

    // ---- prep: weights, degrees, normalization, CSR ----
    k_wt<<<cdiv(512 * 512, 256), 256>>>(W1, wt1h, wt1l, 512, 512);
    k_wt<<<cdiv(256 * 512, 256), 256>>>(W2, wt2h, wt2l, 512, 256);
    k_wt<<<cdiv(512 * 256, 256), 256>>>(W3, wt3h, wt3l, 256, 512);
    k_wt<<<cdiv(256 * 512, 256), 256>>>(W4, wt4h, wt4l, 512, 256);
    k_zero_deg<<<cdiv(N, 256), 256>>>(deg1, deg2, N);
    k_deg<<<cdiv(E1, 256), 256>>>(dst1, E1, deg1);
    k_deg<<<cdiv(E2, 256), 256>>>(dst2, E2, deg2);
    k_inv<<<cdiv(N, 256), 256>>>(deg1, deg2, inv1, inv2, N);
    k_scan2<<<2, 1024>>>(deg1, deg2, rs1, cur1, rs2, cur2, N);
    k_bin<<<cdiv(E1, 256), 256>>>(src1, dst1, inv1, E1, cur1, edges1);
    k_bin<<<cdiv(E2, 256), 256>>>(src2, dst2, inv2, E2, cur2, edges2);

    // ---- Layer 1: GEMM1 (h->b512a, init->b512b); AGG1 epi relu+split -> ah/al ----
    k_cvt<<<cdiv(N * 128, 256), 256>>>(x, ah, al, N * 128);
    k_mmagemm<0><<<dim3(4, rowT), 512, GEMM_SMEM_BYTES>>>(
        ah, al, wt1h, wt1l, b1, inv1, b512a, b512b, N, 512, 512);
    k_agg<512, 1><<<aggB, 256>>>(rs1, edges1, inv1, nullptr, b512a, b512b, ah, al, N);

    // ---- Layer 2: GEMM2 (h->b256a, init->b256b); AGG2 epi relu->out_z, *inv2^2->b256c ----
    k_mmagemm<0><<<dim3(2, rowT), 512, GEMM_SMEM_BYTES>>>(
        ah, al, wt2h, wt2l, b2, inv1, b256a, b256b, N, 256, 512);
    k_agg<256, 2><<<aggB, 256>>>(rs1, edges1, inv1, inv2, b256a, b256b, out_z, b256c, N);

    // ---- Layer 3 (aggregate-first): AGG3 epi split -> ah/al; GEMM3 epi relu+split -> ah2/al2 ----
    k_agg<256, 3><<<aggB, 256>>>(rs2, edges2, inv2, nullptr, out_z, b256c, ah, al, N);
    k_mmagemm<1><<<dim3(4, rowT), 512, GEMM_SMEM_BYTES>>>(
        ah, al, wt3h, wt3l, b3, inv2, ah2, al2, N, 512, 256);

    // ---- Layer 4: GEMM4 (h->b256a, init->b256b); AGG4 epi relu -> out_zg ----
    k_mmagemm<0><<<dim3(2, rowT), 512, GEMM_SMEM_BYTES>>>(
        ah2, al2, wt4h, wt4l, b4, inv2, b256a, b256b, N, 256, 512);
    k_agg<256, 0><<<aggB, 256>>>(rs2, edges2, inv2, nullptr, b256a, b256b, out_zg, nullptr, N);
}

// round 10
// speedup vs baseline: 2.3494x; 1.0037x over previous
#include <cuda_runtime.h>
#include <cuda_bf16.h>
#include <math.h>
#include <stdint.h>

// ---------------------------------------------------------------------------
// GCN encoder stack — HMMA split GEMM + CSR gather-aggregation (no atomics),
// edge-batched (MLP x4) with precomputed per-edge coefficients.
//   z   = relu(A1n(relu(A1n(x W1)+b1) W2)+b2)
//   z_g = relu(A2n(relu((A2n z) W3 + b3) W4)+b4)   (layer3: A(zW)=(Az)W)
// ---------------------------------------------------------------------------

#define NMAX 50048
#define EMAX 400064

__device__ float g_b512a[(size_t)NMAX * 512];   // h1; later aliased as b256c
__device__ float g_b512b[(size_t)NMAX * 512];   // init1/agg1
__device__ float g_b256a[(size_t)NMAX * 256];
__device__ float g_b256b[(size_t)NMAX * 256];
__device__ int   g_deg1[NMAX];
__device__ int   g_deg2[NMAX];
__device__ float g_inv1[NMAX];
__device__ float g_inv2[NMAX];
// CSR
__device__ int   g_rs1[NMAX + 1];
__device__ int   g_rs2[NMAX + 1];
__device__ int   g_cur1[NMAX];
__device__ int   g_cur2[NMAX];
__device__ int2  g_edges1[EMAX];   // .x = src, .y = bitcast(inv[src])
__device__ int2  g_edges2[EMAX];

// bf16 split buffers for GEMM A operands
__device__ __nv_bfloat16 g_ah[(size_t)NMAX * 512];
__device__ __nv_bfloat16 g_al[(size_t)NMAX * 512];
__device__ __nv_bfloat16 g_ah2[(size_t)NMAX * 512];
__device__ __nv_bfloat16 g_al2[(size_t)NMAX * 512];
// pre-transposed weights, K-major [N_out, K], bf16 hi/lo
__device__ __nv_bfloat16 g_wt1h[512 * 512], g_wt1l[512 * 512];
__device__ __nv_bfloat16 g_wt2h[256 * 512], g_wt2l[256 * 512];
__device__ __nv_bfloat16 g_wt3h[512 * 256], g_wt3l[512 * 256];
__device__ __nv_bfloat16 g_wt4h[256 * 512], g_wt4l[256 * 512];

// ---------------------------------------------------------------------------
// PTX helpers
// ---------------------------------------------------------------------------
__device__ __forceinline__ uint32_t smem_u32(const void* p) {
    uint32_t a;
    asm("{ .reg .u64 t; cvta.to.shared.u64 t, %1; cvt.u32.u64 %0, t; }" : "=r"(a) : "l"(p));
    return a;
}

__device__ __forceinline__ void cp_async16(uint32_t dst, const void* src, bool pred) {
    int sz = pred ? 16 : 0;
    asm volatile("cp.async.cg.shared.global [%0], [%1], 16, %2;"
                 :: "r"(dst), "l"(src), "r"(sz) : "memory");
}
#define CP_COMMIT() asm volatile("cp.async.commit_group;" ::: "memory")
#define CP_WAIT(n)  asm volatile("cp.async.wait_group %0;" :: "n"(n) : "memory")

#define LDMATRIX_X4(r0, r1, r2, r3, addr) \
    asm volatile("ldmatrix.sync.aligned.m8n8.x4.shared.b16 {%0,%1,%2,%3}, [%4];" \
                 : "=r"(r0), "=r"(r1), "=r"(r2), "=r"(r3) : "r"(addr))

__device__ __forceinline__ void mma_bf16(float* c, const uint32_t* a, const uint32_t* b) {
    asm volatile(
        "mma.sync.aligned.m16n8k16.row.col.f32.bf16.bf16.f32 "
        "{%0,%1,%2,%3}, {%4,%5,%6,%7}, {%8,%9}, {%0,%1,%2,%3};"
        : "+f"(c[0]), "+f"(c[1]), "+f"(c[2]), "+f"(c[3])
        : "r"(a[0]), "r"(a[1]), "r"(a[2]), "r"(a[3]), "r"(b[0]), "r"(b[1]));
}

// ---------------------------------------------------------------------------
// degree / normalization / CSR build
// ---------------------------------------------------------------------------
__global__ void k_zero_deg(int* d1, int* d2, int n) {
    int i = blockIdx.x * blockDim.x + threadIdx.x;
    if (i < n) { d1[i] = 0; d2[i] = 0; }
}
__global__ void k_deg(const int* __restrict__ dst, int E, int* deg) {
    int i = blockIdx.x * blockDim.x + threadIdx.x;
    if (i < E) atomicAdd(&deg[dst[i]], 1);
}
__global__ void k_inv(const int* __restrict__ d1, const int* __restrict__ d2,
                      float* i1, float* i2, int n) {
    int i = blockIdx.x * blockDim.x + threadIdx.x;
    if (i < n) {
        i1[i] = rsqrtf((float)d1[i] + 1.0f);
        i2[i] = rsqrtf((float)d2[i] + 1.0f);
    }
}

// single-block-per-graph prefix sum: rs[i+1]=cumsum(deg), cur[i]=rs[i]
__global__ __launch_bounds__(1024)
void k_scan2(const int* __restrict__ deg1, const int* __restrict__ deg2,
             int* rs1, int* cur1, int* rs2, int* cur2, int n) {
    const int* deg = blockIdx.x ? deg2 : deg1;
    int* rs  = blockIdx.x ? rs2  : rs1;
    int* cur = blockIdx.x ? cur2 : cur1;
    __shared__ int sm[1024];
    __shared__ int carry;
    int tid = threadIdx.x;
    if (tid == 0) { carry = 0; rs[0] = 0; }
    __syncthreads();
    for (int base = 0; base < n; base += 1024) {
        int i = base + tid;
        int v = (i < n) ? deg[i] : 0;
        sm[tid] = v;
        __syncthreads();
#pragma unroll
        for (int off = 1; off < 1024; off <<= 1) {
            int t = (tid >= off) ? sm[tid - off] : 0;
            __syncthreads();
            sm[tid] += t;
            __syncthreads();
        }
        int inc = sm[tid] + carry;
        if (i < n) { rs[i + 1] = inc; cur[i] = inc - v; }
        __syncthreads();
        if (tid == 1023) carry = inc;
        __syncthreads();
    }
}

// bin edges by dst; store (src, inv[src]) so the agg loop has no dependent load
__global__ void k_bin(const int* __restrict__ src, const int* __restrict__ dst,
                      const float* __restrict__ inv, int E, int* cursor,
                      int2* __restrict__ edges) {
    int i = blockIdx.x * blockDim.x + threadIdx.x;
    if (i < E) {
        int s = src[i];
        int p = atomicAdd(&cursor[dst[i]], 1);
        edges[p] = make_int2(s, __float_as_int(__ldg(inv + s)));
    }
}

// ---------------------------------------------------------------------------
// fp32 -> bf16 hi/lo split (input x only)
// ---------------------------------------------------------------------------
__global__ void k_cvt(const float* __restrict__ in, __nv_bfloat16* __restrict__ hi,
                      __nv_bfloat16* __restrict__ lo, int n4) {
    int i = blockIdx.x * blockDim.x + threadIdx.x;
    if (i >= n4) return;
    float4 v = ((const float4*)in)[i];
    __nv_bfloat16 hx = __float2bfloat16_rn(v.x), hy = __float2bfloat16_rn(v.y);
    __nv_bfloat16 hz = __float2bfloat16_rn(v.z), hw = __float2bfloat16_rn(v.w);
    __nv_bfloat16 lx = __float2bfloat16_rn(v.x - __bfloat162float(hx));
    __nv_bfloat16 ly = __float2bfloat16_rn(v.y - __bfloat162float(hy));
    __nv_bfloat16 lz = __float2bfloat16_rn(v.z - __bfloat162float(hz));
    __nv_bfloat16 lw = __float2bfloat16_rn(v.w - __bfloat162float(hw));
    __nv_bfloat162* H = (__nv_bfloat162*)hi;
    __nv_bfloat162* L = (__nv_bfloat162*)lo;
    H[2 * i]     = __nv_bfloat162(hx, hy);
    H[2 * i + 1] = __nv_bfloat162(hz, hw);
    L[2 * i]     = __nv_bfloat162(lx, ly);
    L[2 * i + 1] = __nv_bfloat162(lz, lw);
}

// weight transpose + split: W[K,N] -> Wt_hi/lo[N,K]
__global__ void k_wt(const float* __restrict__ W, __nv_bfloat16* __restrict__ th,
                     __nv_bfloat16* __restrict__ tl, int K, int N) {
    int idx = blockIdx.x * blockDim.x + threadIdx.x;
    if (idx >= N * K) return;
    int n = idx / K, k = idx - n * K;
    float w = W[(size_t)k * N + n];
    __nv_bfloat16 h = __float2bfloat16_rn(w);
    th[idx] = h;
    tl[idx] = __float2bfloat16_rn(w - __bfloat162float(h));
}

// ---------------------------------------------------------------------------
// CSR aggregation: one warp per dst row, edges batched x4 for MLP.
//   acc = init[row] + sum_e coef_e * h[src_e]
// EPI: 0 = relu -> outA(f32)
//      1 = relu -> bf16 split outA/outB
//      2 = relu -> outA(f32), relu*inv2^2 -> outB(f32)
//      3 = bf16 split outA/outB (no relu)
// ---------------------------------------------------------------------------
template<int D, int EPI>
__global__ __launch_bounds__(256)
void k_agg(const int* __restrict__ row_start, const int2* __restrict__ edges,
           const float* __restrict__ inv, const float* __restrict__ inv2,
           const float* __restrict__ h, const float* __restrict__ init,
           void* __restrict__ outAv, void* __restrict__ outBv, int n) {
    constexpr int Q = D / 128;             // float4 per lane
    int warp = (blockIdx.x * 256 + threadIdx.x) >> 5;
    int lane = threadIdx.x & 31;
    if (warp >= n) return;

    float4 acc[Q];
    const float4* ip = (const float4*)(init + (size_t)warp * D);
#pragma unroll
    for (int q = 0; q < Q; q++) acc[q] = ip[lane + 32 * q];

    const int s0 = row_start[warp];
    const int s1 = row_start[warp + 1];
    const float invd = __ldg(inv + warp);

    int e = s0;
    // batched x4: front-load 4 rows' gathers (MLP = 4*Q)
    for (; e + 4 <= s1; e += 4) {
        int2 e0 = __ldg(edges + e);
        int2 e1 = __ldg(edges + e + 1);
        int2 e2 = __ldg(edges + e + 2);
        int2 e3 = __ldg(edges + e + 3);
        float c0 = __int_as_float(e0.y) * invd;
        float c1 = __int_as_float(e1.y) * invd;
        float c2 = __int_as_float(e2.y) * invd;
        float c3 = __int_as_float(e3.y) * invd;
        const float4* p0 = (const float4*)(h + (size_t)e0.x * D);
        const float4* p1 = (const float4*)(h + (size_t)e1.x * D);
        const float4* p2 = (const float4*)(h + (size_t)e2.x * D);
        const float4* p3 = (const float4*)(h + (size_t)e3.x * D);
        float4 v0[Q], v1[Q], v2[Q], v3[Q];
#pragma unroll
        for (int q = 0; q < Q; q++) v0[q] = p0[lane + 32 * q];
#pragma unroll
        for (int q = 0; q < Q; q++) v1[q] = p1[lane + 32 * q];
#pragma unroll
        for (int q = 0; q < Q; q++) v2[q] = p2[lane + 32 * q];
#pragma unroll
        for (int q = 0; q < Q; q++) v3[q] = p3[lane + 32 * q];
#pragma unroll
        for (int q = 0; q < Q; q++) {
            acc[q].x = fmaf(v0[q].x, c0, acc[q].x);
            acc[q].y = fmaf(v0[q].y, c0, acc[q].y);
            acc[q].z = fmaf(v0[q].z, c0, acc[q].z);
            acc[q].w = fmaf(v0[q].w, c0, acc[q].w);
            acc[q].x = fmaf(v1[q].x, c1, acc[q].x);
            acc[q].y = fmaf(v1[q].y, c1, acc[q].y);
            acc[q].z = fmaf(v1[q].z, c1, acc[q].z);
            acc[q].w = fmaf(v1[q].w, c1, acc[q].w);
            acc[q].x = fmaf(v2[q].x, c2, acc[q].x);
            acc[q].y = fmaf(v2[q].y, c2, acc[q].y);
            acc[q].z = fmaf(v2[q].z, c2, acc[q].z);
            acc[q].w = fmaf(v2[q].w, c2, acc[q].w);
            acc[q].x = fmaf(v3[q].x, c3, acc[q].x);
            acc[q].y = fmaf(v3[q].y, c3, acc[q].y);
            acc[q].z = fmaf(v3[q].z, c3, acc[q].z);
            acc[q].w = fmaf(v3[q].w, c3, acc[q].w);
        }
    }
    // tail
    for (; e < s1; e++) {
        int2 ee = __ldg(edges + e);
        float c = __int_as_float(ee.y) * invd;
        const float4* hp = (const float4*)(h + (size_t)ee.x * D);
#pragma unroll
        for (int q = 0; q < Q; q++) {
            float4 v = hp[lane + 32 * q];
            acc[q].x = fmaf(v.x, c, acc[q].x);
            acc[q].y = fmaf(v.y, c, acc[q].y);
            acc[q].z = fmaf(v.z, c, acc[q].z);
            acc[q].w = fmaf(v.w, c, acc[q].w);
        }
    }

    if (EPI == 0) {
        float* oa = (float*)outAv;
#pragma unroll
        for (int q = 0; q < Q; q++) {
            float4 v = acc[q];
            v.x = fmaxf(v.x, 0.f); v.y = fmaxf(v.y, 0.f);
            v.z = fmaxf(v.z, 0.f); v.w = fmaxf(v.w, 0.f);
            ((float4*)(oa + (size_t)warp * D))[lane + 32 * q] = v;
        }
    } else if (EPI == 2) {
        float* oa = (float*)outAv;
        float* ob = (float*)outBv;
        float sc = __ldg(inv2 + warp); sc *= sc;
#pragma unroll
        for (int q = 0; q < Q; q++) {
            float4 v = acc[q];
            v.x = fmaxf(v.x, 0.f); v.y = fmaxf(v.y, 0.f);
            v.z = fmaxf(v.z, 0.f); v.w = fmaxf(v.w, 0.f);
            ((float4*)(oa + (size_t)warp * D))[lane + 32 * q] = v;
            ((float4*)(ob + (size_t)warp * D))[lane + 32 * q] =
                make_float4(v.x * sc, v.y * sc, v.z * sc, v.w * sc);
        }
    } else {  // EPI 1 / 3: bf16 hi/lo split (EPI 1 applies relu first)
        __nv_bfloat16* CH = (__nv_bfloat16*)outAv;
        __nv_bfloat16* CL = (__nv_bfloat16*)outBv;
#pragma unroll
        for (int q = 0; q < Q; q++) {
            float4 v = acc[q];
            if (EPI == 1) {
                v.x = fmaxf(v.x, 0.f); v.y = fmaxf(v.y, 0.f);
                v.z = fmaxf(v.z, 0.f); v.w = fmaxf(v.w, 0.f);
            }
            __nv_bfloat16 hx = __float2bfloat16_rn(v.x), hy = __float2bfloat16_rn(v.y);
            __nv_bfloat16 hz = __float2bfloat16_rn(v.z), hw = __float2bfloat16_rn(v.w);
            __nv_bfloat16 lx = __float2bfloat16_rn(v.x - __bfloat162float(hx));
            __nv_bfloat16 ly = __float2bfloat16_rn(v.y - __bfloat162float(hy));
            __nv_bfloat16 lz = __float2bfloat16_rn(v.z - __bfloat162float(hz));
            __nv_bfloat16 lw = __float2bfloat16_rn(v.w - __bfloat162float(hw));
            size_t base = (size_t)warp * D + 4 * (lane + 32 * q);
            ((__nv_bfloat162*)(CH + base))[0] = __nv_bfloat162(hx, hy);
            ((__nv_bfloat162*)(CH + base))[1] = __nv_bfloat162(hz, hw);
            ((__nv_bfloat162*)(CL + base))[0] = __nv_bfloat162(lx, ly);
            ((__nv_bfloat162*)(CL + base))[1] = __nv_bfloat162(lz, lw);
        }
    }
}

// ---------------------------------------------------------------------------
// HMMA GEMM: acc[M,N] = A[M,K] * Wt[N,K]^T, fused epilogue:
//   MODE 0: C0 = acc ; C1 = acc*inv[row]^2 + bias[col]
//   MODE 1: v = relu(acc + bias[col]); C0 = bf16_hi(v), C1 = bf16_lo(v)
// ---------------------------------------------------------------------------
#define STAGE_BYTES 65536
#define GEMM_SMEM_BYTES (2 * STAGE_BYTES)

template<int MODE>
__global__ __launch_bounds__(512)
void k_mmagemm(const __nv_bfloat16* __restrict__ Ah, const __nv_bfloat16* __restrict__ Al,
               const __nv_bfloat16* __restrict__ Bh, const __nv_bfloat16* __restrict__ Bl,
               const float* __restrict__ bias, const float* __restrict__ inv,
               void* __restrict__ C0v, void* __restrict__ C1v,
               int M, int N, int K) {
    extern __shared__ uint8_t smem[];
    const uint32_t sb = smem_u32(smem);

    const int tid  = threadIdx.x;
    const int wid  = tid >> 5;
    const int lane = tid & 31;
    const int wr   = wid >> 2;
    const int wc   = wid & 3;
    const int m0   = blockIdx.y * 128;
    const int n0   = blockIdx.x * 128;

    const int lrow = tid >> 3;
    const int lc16 = tid & 7;

    const int a_r = (lane & 7) + ((lane >> 3) & 1) * 8;
    const int a_h = (lane >> 4) & 1;
    const int b_r = (lane & 7) + ((lane >> 4) & 1) * 8;
    const int b_h = (lane >> 3) & 1;

    float acc[2][4][4];
#pragma unroll
    for (int i = 0; i < 2; i++)
#pragma unroll
        for (int j = 0; j < 4; j++)
#pragma unroll
            for (int q = 0; q < 4; q++) acc[i][j][q] = 0.f;

    const int kIters = K >> 6;

    auto load_chunk = [&](int stage, int k0) {
        const uint32_t sbase = sb + stage * STAGE_BYTES;
#pragma unroll
        for (int j = 0; j < 2; j++) {
            const int row = lrow + j * 64;
            const int c16 = lc16;
            const uint32_t soff = (uint32_t)(row * 128 + ((c16 ^ (row & 7)) << 4));
            const bool aok = (m0 + row) < M;
            const int arow = aok ? (m0 + row) : (M - 1);
            const size_t ga = (size_t)arow * K + k0 + c16 * 8;
            cp_async16(sbase + soff,         Ah + ga, aok);
            cp_async16(sbase + 16384 + soff, Al + ga, aok);
            const size_t gb = (size_t)(n0 + row) * K + k0 + c16 * 8;
            cp_async16(sbase + 32768 + soff, Bh + gb, true);
            cp_async16(sbase + 49152 + soff, Bl + gb, true);
        }
        CP_COMMIT();
    };

    load_chunk(0, 0);

    int stage = 0;
    for (int it = 0; it < kIters; it++) {
        if (it + 1 < kIters) load_chunk(stage ^ 1, (it + 1) << 6);
        if (it + 1 < kIters) { CP_WAIT(1); } else { CP_WAIT(0); }
        __syncthreads();

        const uint32_t A_H = sb + stage * STAGE_BYTES;
        const uint32_t A_L = A_H + 16384;
        const uint32_t B_H = A_H + 32768;
        const uint32_t B_L = A_H + 49152;

#pragma unroll
        for (int ks = 0; ks < 4; ks++) {
            uint32_t af_h[2][4], af_l[2][4];
#pragma unroll
            for (int am = 0; am < 2; am++) {
                const int row = wr * 32 + am * 16 + a_r;
                const int c16 = ks * 2 + a_h;
                const uint32_t off = (uint32_t)(row * 128 + ((c16 ^ (row & 7)) << 4));
                LDMATRIX_X4(af_h[am][0], af_h[am][1], af_h[am][2], af_h[am][3], A_H + off);
                LDMATRIX_X4(af_l[am][0], af_l[am][1], af_l[am][2], af_l[am][3], A_L + off);
            }
            uint32_t bf_h[4][2], bf_l[4][2];
#pragma unroll
            for (int bp = 0; bp < 2; bp++) {
                const int row = wc * 32 + bp * 16 + b_r;
                const int c16 = ks * 2 + b_h;
                const uint32_t off = (uint32_t)(row * 128 + ((c16 ^ (row & 7)) << 4));
                uint32_t r0, r1, r2, r3;
                LDMATRIX_X4(r0, r1, r2, r3, B_H + off);
                bf_h[bp * 2][0] = r0; bf_h[bp * 2][1] = r1;
                bf_h[bp * 2 + 1][0] = r2; bf_h[bp * 2 + 1][1] = r3;
                LDMATRIX_X4(r0, r1, r2, r3, B_L + off);
                bf_l[bp * 2][0] = r0; bf_l[bp * 2][1] = r1;
                bf_l[bp * 2 + 1][0] = r2; bf_l[bp * 2 + 1][1] = r3;
            }
#pragma unroll
            for (int am = 0; am < 2; am++)
#pragma unroll
                for (int bn = 0; bn < 4; bn++) {
                    mma_bf16(acc[am][bn], af_h[am], bf_h[bn]);
                    mma_bf16(acc[am][bn], af_h[am], bf_l[bn]);
                    mma_bf16(acc[am][bn], af_l[am], bf_h[bn]);
                }
        }
        __syncthreads();
        stage ^= 1;
    }

    // ---- fused epilogue ----
    const int r_base = m0 + wr * 32 + (lane >> 2);
    const int c_base = n0 + wc * 32 + (lane & 3) * 2;
#pragma unroll
    for (int am = 0; am < 2; am++) {
#pragma unroll
        for (int bn = 0; bn < 4; bn++) {
            const int col = c_base + bn * 8;
            const float bx = __ldg(bias + col), by = __ldg(bias + col + 1);
#pragma unroll
            for (int h = 0; h < 2; h++) {
                const int row = r_base + am * 16 + h * 8;
                if (row < M) {
                    float v0 = acc[am][bn][h * 2];
                    float v1 = acc[am][bn][h * 2 + 1];
                    if (MODE == 0) {
                        float* Ch = (float*)C0v;
                        float* Cg = (float*)C1v;
                        float s = __ldg(inv + row); s *= s;
                        *(float2*)(Ch + (size_t)row * N + col) = make_float2(v0, v1);
                        *(float2*)(Cg + (size_t)row * N + col) =
                            make_float2(v0 * s + bx, v1 * s + by);
                    } else {
                        float u0 = fmaxf(v0 + bx, 0.f);
                        float u1 = fmaxf(v1 + by, 0.f);
                        __nv_bfloat16 h0 = __float2bfloat16_rn(u0);
                        __nv_bfloat16 h1 = __float2bfloat16_rn(u1);
                        __nv_bfloat16 l0 = __float2bfloat16_rn(u0 - __bfloat162float(h0));
                        __nv_bfloat16 l1 = __float2bfloat16_rn(u1 - __bfloat162float(h1));
                        __nv_bfloat16* CH = (__nv_bfloat16*)C0v;
                        __nv_bfloat16* CL = (__nv_bfloat16*)C1v;
                        *(__nv_bfloat162*)(CH + (size_t)row * N + col) = __nv_bfloat162(h0, h1);
                        *(__nv_bfloat162*)(CL + (size_t)row * N + col) = __nv_bfloat162(l0, l1);
                    }
                }
            }
        }
    }
}

// ---------------------------------------------------------------------------
// launch
// ---------------------------------------------------------------------------
static inline int cdiv(int a, int b) { return (a + b - 1) / b; }

extern "C" void kernel_launch(void* const* d_in, const int* in_sizes, int n_in,
                              void* d_out, int out_size) {
    if (n_in < 11) return;
    const float* x  = (const float*)d_in[0];
    const int* ei1  = (const int*)d_in[1];
    const int* ei2  = (const int*)d_in[2];
    const float* W1 = (const float*)d_in[3];
    const float* b1 = (const float*)d_in[4];
    const float* W2 = (const float*)d_in[5];
    const float* b2 = (const float*)d_in[6];
    const float* W3 = (const float*)d_in[7];
    const float* b3 = (const float*)d_in[8];
    const float* W4 = (const float*)d_in[9];
    const float* b4 = (const float*)d_in[10];

    const int N  = in_sizes[0] / 512;
    const int E1 = in_sizes[1] / 2;
    const int E2 = in_sizes[2] / 2;
    const int* src1 = ei1;
    const int* dst1 = ei1 + E1;
    const int* src2 = ei2;
    const int* dst2 = ei2 + E2;

    float *b512a, *b512b, *b256a, *b256b, *inv1, *inv2;
    int *deg1, *deg2, *rs1, *rs2, *cur1, *cur2;
    int2 *edges1, *edges2;
    __nv_bfloat16 *ah, *al, *ah2, *al2;
    __nv_bfloat16 *wt1h, *wt1l, *wt2h, *wt2l, *wt3h, *wt3l, *wt4h, *wt4l;
    cudaGetSymbolAddress((void**)&b512a, g_b512a);
    cudaGetSymbolAddress((void**)&b512b, g_b512b);
    cudaGetSymbolAddress((void**)&b256a, g_b256a);
    cudaGetSymbolAddress((void**)&b256b, g_b256b);
    cudaGetSymbolAddress((void**)&deg1,  g_deg1);
    cudaGetSymbolAddress((void**)&deg2,  g_deg2);
    cudaGetSymbolAddress((void**)&inv1,  g_inv1);
    cudaGetSymbolAddress((void**)&inv2,  g_inv2);
    cudaGetSymbolAddress((void**)&rs1,   g_rs1);
    cudaGetSymbolAddress((void**)&rs2,   g_rs2);
    cudaGetSymbolAddress((void**)&cur1,  g_cur1);
    cudaGetSymbolAddress((void**)&cur2,  g_cur2);
    cudaGetSymbolAddress((void**)&edges1, g_edges1);
    cudaGetSymbolAddress((void**)&edges2, g_edges2);
    cudaGetSymbolAddress((void**)&ah,    g_ah);
    cudaGetSymbolAddress((void**)&al,    g_al);
    cudaGetSymbolAddress((void**)&ah2,   g_ah2);
    cudaGetSymbolAddress((void**)&al2,   g_al2);
    cudaGetSymbolAddress((void**)&wt1h,  g_wt1h);  cudaGetSymbolAddress((void**)&wt1l, g_wt1l);
    cudaGetSymbolAddress((void**)&wt2h,  g_wt2h);  cudaGetSymbolAddress((void**)&wt2l, g_wt2l);
    cudaGetSymbolAddress((void**)&wt3h,  g_wt3h);  cudaGetSymbolAddress((void**)&wt3l, g_wt3l);
    cudaGetSymbolAddress((void**)&wt4h,  g_wt4h);  cudaGetSymbolAddress((void**)&wt4l, g_wt4l);

    float* b256c = b512a;  // alias: h1 region free after AGG1

    cudaFuncSetAttribute(k_mmagemm<0>,
                         cudaFuncAttributeMaxDynamicSharedMemorySize, GEMM_SMEM_BYTES);
    cudaFuncSetAttribute(k_mmagemm<1>,
                         cudaFuncAttributeMaxDynamicSharedMemorySize, GEMM_SMEM_BYTES);

    float* out_z  = (float*)d_out;
    float* out_zg = out_z + (size_t)N * 256;
    const int rowT = cdiv(N, 128);
    const int aggB = cdiv(N * 32, 256);

    // ---- prep: weights, degrees, normalization, CSR ----
    k_wt<<<cdiv(512 * 512, 256), 256>>>(W1, wt1h, wt1l, 512, 512);
    k_wt<<<cdiv(256 * 512, 256), 256>>>(W2, wt2h, wt2l, 512, 256);
    k_wt<<<cdiv(512 * 256, 256), 256>>>(W3, wt3h, wt3l, 256, 512);
    k_wt<<<cdiv(256 * 512, 256), 256>>>(W4, wt4h, wt4l, 512, 256);
    k_zero_deg<<<cdiv(N, 256), 256>>>(deg1, deg2, N);
    k_deg<<<cdiv(E1, 256), 256>>>(dst1, E1, deg1);
    k_deg<<<cdiv(E2, 256), 256>>>(dst2, E2, deg2);
    k_inv<<<cdiv(N, 256), 256>>>(deg1, deg2, inv1, inv2, N);
    k_scan2<<<2, 1024>>>(deg1, deg2, rs1, cur1, rs2, cur2, N);
    k_bin<<<cdiv(E1, 256), 256>>>(src1, dst1, inv1, E1, cur1, edges1);
    k_bin<<<cdiv(E2, 256), 256>>>(src2, dst2, inv2, E2, cur2, edges2);

    // ---- Layer 1: GEMM1 (h->b512a, init->b512b); AGG1 epi relu+split -> ah/al ----
    k_cvt<<<cdiv(N * 128, 256), 256>>>(x, ah, al, N * 128);
    k_mmagemm<0><<<dim3(4, rowT), 512, GEMM_SMEM_BYTES>>>(
        ah, al, wt1h, wt1l, b1, inv1, b512a, b512b, N, 512, 512);
    k_agg<512, 1><<<aggB, 256>>>(rs1, edges1, inv1, nullptr, b512a, b512b, ah, al, N);

    // ---- Layer 2: GEMM2 (h->b256a, init->b256b); AGG2 epi relu->out_z, *inv2^2->b256c ----
    k_mmagemm<0><<<dim3(2, rowT), 512, GEMM_SMEM_BYTES>>>(
        ah, al, wt2h, wt2l, b2, inv1, b256a, b256b, N, 256, 512);
    k_agg<256, 2><<<aggB, 256>>>(rs1, edges1, inv1, inv2, b256a, b256b, out_z, b256c, N);

    // ---- Layer 3 (aggregate-first): AGG3 epi split -> ah/al; GEMM3 epi relu+split -> ah2/al2 ----
    k_agg<256, 3><<<aggB, 256>>>(rs2, edges2, inv2, nullptr, out_z, b256c, ah, al, N);
    k_mmagemm<1><<<dim3(4, rowT), 512, GEMM_SMEM_BYTES>>>(
        ah, al, wt3h, wt3l, b3, inv2, ah2, al2, N, 512, 256);

    // ---- Layer 4: GEMM4 (h->b256a, init->b256b); AGG4 epi relu -> out_zg ----
    k_mmagemm<0><<<dim3(2, rowT), 512, GEMM_SMEM_BYTES>>>(
        ah2, al2, wt4h, wt4l, b4, inv2, b256a, b256b, N, 256, 512);
    k_agg<256, 0><<<aggB, 256>>>(rs2, edges2, inv2, nullptr, b256a, b256b, out_zg, nullptr, N);
}